// round 10
// baseline (speedup 1.0000x reference)
#include <cuda_runtime.h>
#include <cuda_bf16.h>
#include <cstdint>

#define NPTS 262144         // 2^18 points
#define CSH  18             // log2(NPTS)
#define CMSK 0x3FFFFu
#define DIMS 10
#define DD   286            // comb(13,3)
#define KT   288            // K padded: 18 ksteps of 16
#define ROWE 296            // A/B row stride in bf16 elems (592 B)
#define ROWB 592            // row stride bytes
#define NB   32             // N columns per streamed B chunk
#define NCH  9              // 288 / 32 chunks
#define CHB  (NB * ROWB * 2)   // bytes per chunk (Bh + Bl) = 37888
#define BM   128
#define ONEI 10             // sentinel index -> ones row

typedef unsigned long long ull;

// B images of symmetrized upper-tri S (S[k][n] = k<n: M[k][n]+M[n][k];
// k==n: M[n][n]; else 0), exact smem layout [chunk 9][Bh 32x592 | Bl 32x592].
__device__ uint4 g_B[NCH * CHB / 16];
__device__ float g_ones[NPTS];
// Monomial index table, reference _exponent_nk order: i0 | i1<<8 | i2<<16.
__device__ uint32_t g_tab[DD];

// ---------------------------------------------------------------------------
// k_prep: B image + ones row + monomial table.
// ---------------------------------------------------------------------------
__global__ void k_prep(const float* __restrict__ M) {
    int idx = blockIdx.x * blockDim.x + threadIdx.x;
    if (idx < NPTS) g_ones[idx] = 1.0f;
    if (idx < KT * KT) {
        int n = idx / KT, k = idx - n * KT;
        float v = 0.0f;
        if (n < DD && k < DD) {
            if (k < n)       v = M[k * DD + n] + M[n * DD + k];
            else if (k == n) v = M[n * DD + n];
        }
        __nv_bfloat16 vh = __float2bfloat16(v);
        __nv_bfloat16 vl = __float2bfloat16(v - __bfloat162float(vh));
        __nv_bfloat16* B = reinterpret_cast<__nv_bfloat16*>(g_B);
        size_t cb = (size_t)(n >> 5) * (CHB / 2);
        size_t off = cb + (size_t)(n & 31) * ROWE + k;
        B[off] = vh;
        B[off + NB * ROWE] = vl;
    }
    if (idx == 0) {
        int r = 0;
        g_tab[r++] = ONEI | (ONEI << 8) | (ONEI << 16);
        for (int j = 0; j < DIMS; j++)
            g_tab[r++] = j | (ONEI << 8) | (ONEI << 16);
        for (int j = 0; j < DIMS; j++)
            for (int a = j; a < DIMS; a++)
                g_tab[r++] = j | (a << 8) | (ONEI << 16);
        for (int j = 0; j < DIMS; j++)
            for (int a = j; a < DIMS; a++)
                for (int b = a; b < DIMS; b++)
                    g_tab[r++] = j | (a << 8) | (b << 16);
    }
}

// ---------------------------------------------------------------------------
// Base-ISA PTX helpers.
// ---------------------------------------------------------------------------
__device__ __forceinline__ void ldsm4(uint32_t r[4], uint32_t addr) {
    asm volatile(
        "ldmatrix.sync.aligned.m8n8.x4.shared.b16 {%0,%1,%2,%3}, [%4];"
        : "=r"(r[0]), "=r"(r[1]), "=r"(r[2]), "=r"(r[3]) : "r"(addr));
}
__device__ __forceinline__ void mma_bf16(float c[4], const uint32_t a[4],
                                         uint32_t b0, uint32_t b1) {
    asm volatile(
        "mma.sync.aligned.m16n8k16.row.col.f32.bf16.bf16.f32 "
        "{%0,%1,%2,%3}, {%4,%5,%6,%7}, {%8,%9}, {%0,%1,%2,%3};"
        : "+f"(c[0]), "+f"(c[1]), "+f"(c[2]), "+f"(c[3])
        : "r"(a[0]), "r"(a[1]), "r"(a[2]), "r"(a[3]), "r"(b0), "r"(b1));
}
__device__ __forceinline__ void bulk_g2s(uint32_t dst, const void* src,
                                         uint32_t bytes, uint32_t mbar) {
    asm volatile(
        "cp.async.bulk.shared::cta.global.mbarrier::complete_tx::bytes "
        "[%0], [%1], %2, [%3];"
        :: "r"(dst), "l"(src), "r"(bytes), "r"(mbar) : "memory");
}
__device__ __forceinline__ void mbar_init(uint32_t mbar, uint32_t cnt) {
    asm volatile("mbarrier.init.shared.b64 [%0], %1;" :: "r"(mbar), "r"(cnt)
                 : "memory");
}
__device__ __forceinline__ void mbar_expect(uint32_t mbar, uint32_t bytes) {
    asm volatile("mbarrier.arrive.expect_tx.shared.b64 _, [%0], %1;"
                 :: "r"(mbar), "r"(bytes) : "memory");
}
__device__ __forceinline__ void mbar_arrive(uint32_t mbar) {
    asm volatile("mbarrier.arrive.shared.b64 _, [%0];" :: "r"(mbar)
                 : "memory");
}
__device__ __forceinline__ void mbar_wait(uint32_t mbar, uint32_t parity) {
    asm volatile(
        "{\n\t.reg .pred P1;\n\t"
        "W_%=:\n\t"
        "mbarrier.try_wait.parity.acquire.cta.shared::cta.b64 P1, [%0], %1, 0x989680;\n\t"
        "@P1 bra.uni D_%=;\n\t"
        "bra.uni W_%=;\n\t"
        "D_%=:\n\t}"
        :: "r"(mbar), "r"(parity) : "memory");
}
__device__ __forceinline__ uint32_t cvt2bf(float hi, float lo) {
    uint32_t r;
    asm("cvt.rn.bf16x2.f32 %0, %1, %2;" : "=r"(r) : "f"(hi), "f"(lo));
    return r;
}
__device__ __forceinline__ const float* mono_ptr(const float* X, uint32_t i) {
    return (i < DIMS) ? (X + (size_t)i * NPTS) : g_ones;
}

// SMEM map
constexpr int SM_FULL0 = 0, SM_EMPTY0 = 16;
constexpr int SM_AH = 1024;
constexpr int SM_AL = SM_AH + BM * ROWB;       // 76800
constexpr int SM_B  = SM_AL + BM * ROWB;       // 152576
constexpr int SMEM_TOTAL = SM_B + 2 * CHB;     // 228352

// ---------------------------------------------------------------------------
// Producer: copy the TRIANGULAR PREFIX of chunk `cn` into buffer `b2`.
// Each of the 64 rows (32 n-rows x 2 splits) gets its used k-prefix only:
// 64*(cn+1) bytes (16-B multiple). ldsm for chunk cn reads k < 32*(cn+1),
// i.e. exactly within the prefix.
// ---------------------------------------------------------------------------
__device__ __forceinline__ void copy_chunk(uint32_t smb, int cn, int b2) {
    const uint32_t bytes = 64u * (cn + 1);
    mbar_expect(smb + SM_FULL0 + 8 * b2, 64u * bytes);
    const char* src = reinterpret_cast<const char*>(g_B) + (size_t)cn * CHB;
    const uint32_t dst = smb + SM_B + b2 * CHB;
#pragma unroll 4
    for (int r = 0; r < 64; r++)
        bulk_g2s(dst + r * ROWB, src + r * ROWB, bytes,
                 smb + SM_FULL0 + 8 * b2);
}

// ---------------------------------------------------------------------------
// k_main: direct A build from L2-resident x -> double-buffered triangular
// B stream + 3-product HMMA GEMM (fully static unroll) + fused T·q epilogue.
// ---------------------------------------------------------------------------
__global__ __launch_bounds__(256, 1) void k_main(const float* __restrict__ X,
                                                 float* __restrict__ out) {
    extern __shared__ char sm[];
    const uint32_t smb = (uint32_t)__cvta_generic_to_shared(sm);
    const int tid = threadIdx.x, w = tid >> 5, lane = tid & 31;

    if (tid == 0) {
        mbar_init(smb + SM_FULL0, 1);
        mbar_init(smb + SM_FULL0 + 8, 1);
        mbar_init(smb + SM_EMPTY0, 256);
        mbar_init(smb + SM_EMPTY0 + 8, 256);
    }
    __syncthreads();
    if (tid == 0) copy_chunk(smb, 0, 0);   // overlaps A build

    // ---- A build: warp w builds rows 16w..16w+15 directly from x ----
#pragma unroll
    for (int rr = 0; rr < 16; rr++) {
        const int row = w * 16 + rr;
        const int n = blockIdx.x * BM + row;
        const uint32_t flat0 = (uint32_t)n * (uint32_t)DD;
        char* ah = sm + SM_AH + row * ROWB;
        char* al = sm + SM_AL + row * ROWB;
        const uint32_t c0 = flat0 & CMSK;    // always even (286 even)
        if (c0 + DD <= NPTS) {   // fast path: one monomial, contiguous window
            const uint32_t t = __ldg(g_tab + (flat0 >> CSH));
            const float* p0 = mono_ptr(X, t & 0xffu) + c0;
            const float* p1 = mono_ptr(X, (t >> 8) & 0xffu) + c0;
            const float* p2 = mono_ptr(X, (t >> 16) & 0xffu) + c0;
            for (int ip = lane; ip < 143; ip += 32) {   // 143 f32 pairs = 286
                float2 a0 = *reinterpret_cast<const float2*>(p0 + 2 * ip);
                float2 a1 = *reinterpret_cast<const float2*>(p1 + 2 * ip);
                float2 a2 = *reinterpret_cast<const float2*>(p2 + 2 * ip);
                float v0 = (a0.x * a1.x) * a2.x;
                float v1 = (a0.y * a1.y) * a2.y;
                uint32_t h2 = cvt2bf(v1, v0);
                float h0 = __uint_as_float(h2 << 16);
                float h1 = __uint_as_float(h2 & 0xffff0000u);
                uint32_t l2 = cvt2bf(v1 - h1, v0 - h0);
                *reinterpret_cast<uint32_t*>(ah + ip * 4) = h2;
                *reinterpret_cast<uint32_t*>(al + ip * 4) = l2;
            }
        } else {                 // rare straddle: per-element
            for (int i = lane; i < DD; i += 32) {
                const uint32_t f = flat0 + i;
                const uint32_t t = __ldg(g_tab + (f >> CSH));
                const uint32_t c = f & CMSK;
                float v = (__ldg(mono_ptr(X, t & 0xffu) + c) *
                           __ldg(mono_ptr(X, (t >> 8) & 0xffu) + c)) *
                          __ldg(mono_ptr(X, (t >> 16) & 0xffu) + c);
                __nv_bfloat16 vh = __float2bfloat16(v);
                __nv_bfloat16 vl = __float2bfloat16(v - __bfloat162float(vh));
                *reinterpret_cast<__nv_bfloat16*>(ah + i * 2) = vh;
                *reinterpret_cast<__nv_bfloat16*>(al + i * 2) = vl;
            }
        }
        if (lane < 2) {          // zero pad i = 286, 287
            *reinterpret_cast<uint32_t*>(ah + 572) = 0u;
            *reinterpret_cast<uint32_t*>(al + 572) = 0u;
        }
    }
    __syncthreads();

    const uint32_t aRow = smb + SM_AH + (w * 16 + (lane & 15)) * ROWB +
                          (lane >> 4) * 16;
    const uint32_t bOff = (((lane >> 4) & 1) * 8 + (lane & 7)) * ROWB +
                          ((lane >> 3) & 1) * 16;

    float out0 = 0.f, out1 = 0.f;
    const int r0 = w * 16 + (lane >> 2);
    const uint32_t qh0 = smb + SM_AH + r0 * ROWB + (lane & 3) * 4;
    const uint32_t ql0 = smb + SM_AL + r0 * ROWB + (lane & 3) * 4;

#pragma unroll
    for (int c = 0; c < NCH; c++) {          // FULLY UNROLLED: kmax static
        const int b = c & 1;
        if (c + 1 < NCH) {
            const int b2 = (c + 1) & 1;
            if (tid == 0) {
                if (c >= 1)
                    mbar_wait(smb + SM_EMPTY0 + 8 * b2, ((c - 1) >> 1) & 1);
                copy_chunk(smb, c + 1, b2);
            }
        }
        mbar_wait(smb + SM_FULL0 + 8 * b, (c >> 1) & 1);

        const uint32_t bh = smb + SM_B + b * CHB + bOff;
        const uint32_t bl = bh + NB * ROWB;

        float C[3][4][4];
#pragma unroll
        for (int p = 0; p < 3; p++)
#pragma unroll
            for (int g = 0; g < 4; g++)
#pragma unroll
                for (int u = 0; u < 4; u++) C[p][g][u] = 0.f;

        const int kmax = 2 * c + 2;          // compile-time under unroll

        uint32_t fah[2][4], fal[2][4];
        uint32_t fh0[2][4], fh1[2][4], fl0[2][4], fl1[2][4];
        ldsm4(fah[0], aRow);
        ldsm4(fal[0], aRow + (SM_AL - SM_AH));
        ldsm4(fh0[0], bh);
        ldsm4(fh1[0], bh + 16 * ROWB);
        ldsm4(fl0[0], bl);
        ldsm4(fl1[0], bl + 16 * ROWB);

#pragma unroll
        for (int k = 0; k < kmax; k++) {
            const int cur = k & 1, nxt = cur ^ 1;
            if (k + 1 < kmax) {
                const uint32_t ko = (k + 1) * 32;
                ldsm4(fah[nxt], aRow + ko);
                ldsm4(fal[nxt], aRow + (SM_AL - SM_AH) + ko);
                ldsm4(fh0[nxt], bh + ko);
                ldsm4(fh1[nxt], bh + 16 * ROWB + ko);
                ldsm4(fl0[nxt], bl + ko);
                ldsm4(fl1[nxt], bl + 16 * ROWB + ko);
            }
            mma_bf16(C[0][0], fah[cur], fh0[cur][0], fh0[cur][1]);
            mma_bf16(C[0][1], fah[cur], fh0[cur][2], fh0[cur][3]);
            mma_bf16(C[0][2], fah[cur], fh1[cur][0], fh1[cur][1]);
            mma_bf16(C[0][3], fah[cur], fh1[cur][2], fh1[cur][3]);
            mma_bf16(C[1][0], fah[cur], fl0[cur][0], fl0[cur][1]);
            mma_bf16(C[1][1], fah[cur], fl0[cur][2], fl0[cur][3]);
            mma_bf16(C[1][2], fah[cur], fl1[cur][0], fl1[cur][1]);
            mma_bf16(C[1][3], fah[cur], fl1[cur][2], fl1[cur][3]);
            mma_bf16(C[2][0], fal[cur], fh0[cur][0], fh0[cur][1]);
            mma_bf16(C[2][1], fal[cur], fh0[cur][2], fh0[cur][3]);
            mma_bf16(C[2][2], fal[cur], fh1[cur][0], fh1[cur][1]);
            mma_bf16(C[2][3], fal[cur], fh1[cur][2], fh1[cur][3]);
        }
        mbar_arrive(smb + SM_EMPTY0 + 8 * b);

        // ---- Fused epilogue: out += (C0+C1+C2) ∘ q over 32 columns ----
        const int jb = c * 32;
#pragma unroll
        for (int nc = 0; nc < 4; nc++) {
            const uint32_t jo = (jb + nc * 8) * 2;
            uint32_t vh, vl, wh, wl;
            asm volatile("ld.shared.b32 %0, [%1];" : "=r"(vh) : "r"(qh0 + jo));
            asm volatile("ld.shared.b32 %0, [%1];" : "=r"(vl) : "r"(ql0 + jo));
            asm volatile("ld.shared.b32 %0, [%1];" : "=r"(wh)
                         : "r"(qh0 + 8 * ROWB + jo));
            asm volatile("ld.shared.b32 %0, [%1];" : "=r"(wl)
                         : "r"(ql0 + 8 * ROWB + jo));
            float qe = __uint_as_float(vh << 16) + __uint_as_float(vl << 16);
            float qo = __uint_as_float(vh & 0xffff0000u) +
                       __uint_as_float(vl & 0xffff0000u);
            float re = __uint_as_float(wh << 16) + __uint_as_float(wl << 16);
            float ro = __uint_as_float(wh & 0xffff0000u) +
                       __uint_as_float(wl & 0xffff0000u);
            float t0 = C[0][nc][0] + C[1][nc][0] + C[2][nc][0];
            float t1 = C[0][nc][1] + C[1][nc][1] + C[2][nc][1];
            float t2 = C[0][nc][2] + C[1][nc][2] + C[2][nc][2];
            float t3 = C[0][nc][3] + C[1][nc][3] + C[2][nc][3];
            out0 = fmaf(t0, qe, out0);
            out0 = fmaf(t1, qo, out0);
            out1 = fmaf(t2, re, out1);
            out1 = fmaf(t3, ro, out1);
        }
    }

    out0 += __shfl_xor_sync(0xffffffffu, out0, 1);
    out0 += __shfl_xor_sync(0xffffffffu, out0, 2);
    out1 += __shfl_xor_sync(0xffffffffu, out1, 1);
    out1 += __shfl_xor_sync(0xffffffffu, out1, 2);
    if ((lane & 3) == 0) {
        out[blockIdx.x * BM + r0]     = out0;
        out[blockIdx.x * BM + r0 + 8] = out1;
    }
}

// ---------------------------------------------------------------------------
// Launch
// ---------------------------------------------------------------------------
extern "C" void kernel_launch(void* const* d_in, const int* in_sizes, int n_in,
                              void* d_out, int out_size) {
    const float* X = (const float*)d_in[0];   // x flat (xr[k][c] = X[k*NPTS+c])
    const float* M = (const float*)d_in[1];   // M_inv 286x286
    float* out = (float*)d_out;

    k_prep<<<NPTS / 256, 256>>>(M);

    cudaFuncSetAttribute(k_main, cudaFuncAttributeMaxDynamicSharedMemorySize,
                         SMEM_TOTAL);
    k_main<<<NPTS / BM, 256, SMEM_TOTAL>>>(X, out);
}

// round 11
// speedup vs baseline: 1.8048x; 1.8048x over previous
#include <cuda_runtime.h>
#include <cuda_bf16.h>
#include <cstdint>

#define NPTS 262144         // 2^18 points
#define CSH  18             // log2(NPTS)
#define CMSK 0x3FFFFu
#define DIMS 10
#define DD   286            // comb(13,3)
#define KT   288            // K padded: 18 ksteps of 16
#define ROWE 296            // A/B row stride in bf16 elems (592 B)
#define ROWB 592            // row stride bytes
#define NB   32             // N columns per streamed B chunk
#define NCH  9              // 288 / 32 chunks
#define CHB  (NB * ROWB * 2)   // bytes per chunk (Bh + Bl) = 37888
#define BM   128
#define THREADS 512
#define ONEI 10             // sentinel index -> ones row

typedef unsigned long long ull;

// B images of symmetrized upper-tri S (S[k][n] = k<n: M[k][n]+M[n][k];
// k==n: M[n][n]; else 0), exact smem layout [chunk 9][Bh 32x592 | Bl 32x592].
__device__ uint4 g_B[NCH * CHB / 16];
__device__ float g_ones[NPTS];
// Monomial index table, reference _exponent_nk order: i0 | i1<<8 | i2<<16.
__device__ uint32_t g_tab[DD];

// ---------------------------------------------------------------------------
// k_prep: B image + ones row + monomial table.
// ---------------------------------------------------------------------------
__global__ void k_prep(const float* __restrict__ M) {
    int idx = blockIdx.x * blockDim.x + threadIdx.x;
    if (idx < NPTS) g_ones[idx] = 1.0f;
    if (idx < KT * KT) {
        int n = idx / KT, k = idx - n * KT;
        float v = 0.0f;
        if (n < DD && k < DD) {
            if (k < n)       v = M[k * DD + n] + M[n * DD + k];
            else if (k == n) v = M[n * DD + n];
        }
        __nv_bfloat16 vh = __float2bfloat16(v);
        __nv_bfloat16 vl = __float2bfloat16(v - __bfloat162float(vh));
        __nv_bfloat16* B = reinterpret_cast<__nv_bfloat16*>(g_B);
        size_t cb = (size_t)(n >> 5) * (CHB / 2);
        size_t off = cb + (size_t)(n & 31) * ROWE + k;
        B[off] = vh;
        B[off + NB * ROWE] = vl;
    }
    if (idx == 0) {
        int r = 0;
        g_tab[r++] = ONEI | (ONEI << 8) | (ONEI << 16);
        for (int j = 0; j < DIMS; j++)
            g_tab[r++] = j | (ONEI << 8) | (ONEI << 16);
        for (int j = 0; j < DIMS; j++)
            for (int a = j; a < DIMS; a++)
                g_tab[r++] = j | (a << 8) | (ONEI << 16);
        for (int j = 0; j < DIMS; j++)
            for (int a = j; a < DIMS; a++)
                for (int b = a; b < DIMS; b++)
                    g_tab[r++] = j | (a << 8) | (b << 16);
    }
}

// ---------------------------------------------------------------------------
// Base-ISA PTX helpers.
// ---------------------------------------------------------------------------
__device__ __forceinline__ void ldsm4(uint32_t r[4], uint32_t addr) {
    asm volatile(
        "ldmatrix.sync.aligned.m8n8.x4.shared.b16 {%0,%1,%2,%3}, [%4];"
        : "=r"(r[0]), "=r"(r[1]), "=r"(r[2]), "=r"(r[3]) : "r"(addr));
}
__device__ __forceinline__ void mma_bf16(float c[4], const uint32_t a[4],
                                         uint32_t b0, uint32_t b1) {
    asm volatile(
        "mma.sync.aligned.m16n8k16.row.col.f32.bf16.bf16.f32 "
        "{%0,%1,%2,%3}, {%4,%5,%6,%7}, {%8,%9}, {%0,%1,%2,%3};"
        : "+f"(c[0]), "+f"(c[1]), "+f"(c[2]), "+f"(c[3])
        : "r"(a[0]), "r"(a[1]), "r"(a[2]), "r"(a[3]), "r"(b0), "r"(b1));
}
__device__ __forceinline__ void bulk_g2s(uint32_t dst, const void* src,
                                         uint32_t bytes, uint32_t mbar) {
    asm volatile(
        "cp.async.bulk.shared::cta.global.mbarrier::complete_tx::bytes "
        "[%0], [%1], %2, [%3];"
        :: "r"(dst), "l"(src), "r"(bytes), "r"(mbar) : "memory");
}
__device__ __forceinline__ void mbar_init(uint32_t mbar, uint32_t cnt) {
    asm volatile("mbarrier.init.shared.b64 [%0], %1;" :: "r"(mbar), "r"(cnt)
                 : "memory");
}
__device__ __forceinline__ void mbar_expect(uint32_t mbar, uint32_t bytes) {
    asm volatile("mbarrier.arrive.expect_tx.shared.b64 _, [%0], %1;"
                 :: "r"(mbar), "r"(bytes) : "memory");
}
__device__ __forceinline__ void mbar_arrive(uint32_t mbar) {
    asm volatile("mbarrier.arrive.shared.b64 _, [%0];" :: "r"(mbar)
                 : "memory");
}
__device__ __forceinline__ void mbar_wait(uint32_t mbar, uint32_t parity) {
    asm volatile(
        "{\n\t.reg .pred P1;\n\t"
        "W_%=:\n\t"
        "mbarrier.try_wait.parity.acquire.cta.shared::cta.b64 P1, [%0], %1, 0x989680;\n\t"
        "@P1 bra.uni D_%=;\n\t"
        "bra.uni W_%=;\n\t"
        "D_%=:\n\t}"
        :: "r"(mbar), "r"(parity) : "memory");
}
__device__ __forceinline__ uint32_t cvt2bf(float hi, float lo) {
    uint32_t r;
    asm("cvt.rn.bf16x2.f32 %0, %1, %2;" : "=r"(r) : "f"(hi), "f"(lo));
    return r;
}
__device__ __forceinline__ const float* mono_ptr(const float* X, uint32_t i) {
    return (i < DIMS) ? (X + (size_t)i * NPTS) : g_ones;
}

// SMEM map
constexpr int SM_FULL0 = 0, SM_EMPTY0 = 16;
constexpr int SM_SR = 32;                      // [2][BM] partial sums (1 KB)
constexpr int SM_AH = 1056;
constexpr int SM_AL = SM_AH + BM * ROWB;       // +75776
constexpr int SM_B  = SM_AL + BM * ROWB;
constexpr int SMEM_TOTAL = SM_B + 2 * CHB;     // ~228.4 KB

// ---------------------------------------------------------------------------
// k_main: direct A build from L2-resident x -> double-buffered B stream +
// triangular 3-product HMMA GEMM, 16 warps (8 row-groups x 2 N-halves).
// ---------------------------------------------------------------------------
__global__ __launch_bounds__(THREADS, 1) void k_main(
        const float* __restrict__ X, float* __restrict__ out) {
    extern __shared__ char sm[];
    const uint32_t smb = (uint32_t)__cvta_generic_to_shared(sm);
    const int tid = threadIdx.x, w = tid >> 5, lane = tid & 31;
    const int wr = w >> 1;         // row group 0..7 (rows 16*wr..16*wr+15)
    const int h  = w & 1;          // N half 0/1 (chunk cols 16h..16h+15)

    if (tid == 0) {
        mbar_init(smb + SM_FULL0, 1);
        mbar_init(smb + SM_FULL0 + 8, 1);
        mbar_init(smb + SM_EMPTY0, THREADS);
        mbar_init(smb + SM_EMPTY0 + 8, THREADS);
    }
    __syncthreads();
    if (tid == 0) {    // kick chunk 0 copy; overlaps A build
        mbar_expect(smb + SM_FULL0, CHB);
        bulk_g2s(smb + SM_B, g_B, CHB, smb + SM_FULL0);
    }

    // ---- A build: warp w builds 8 rows directly from L2-resident x ----
#pragma unroll
    for (int rr = 0; rr < 8; rr++) {
        const int row = w * 8 + rr;
        const int n = blockIdx.x * BM + row;
        const uint32_t flat0 = (uint32_t)n * (uint32_t)DD;
        char* ah = sm + SM_AH + row * ROWB;
        char* al = sm + SM_AL + row * ROWB;
        const uint32_t c0 = flat0 & CMSK;      // even (286 even)
        if (c0 + DD <= NPTS) {   // fast path: one monomial, contiguous window
            const uint32_t t = __ldg(g_tab + (flat0 >> CSH));
            const float* p0 = mono_ptr(X, t & 0xffu) + c0;
            const float* p1 = mono_ptr(X, (t >> 8) & 0xffu) + c0;
            const float* p2 = mono_ptr(X, (t >> 16) & 0xffu) + c0;
            for (int ip = lane; ip < 143; ip += 32) {   // 143 f32 pairs
                float2 a0 = *reinterpret_cast<const float2*>(p0 + 2 * ip);
                float2 a1 = *reinterpret_cast<const float2*>(p1 + 2 * ip);
                float2 a2 = *reinterpret_cast<const float2*>(p2 + 2 * ip);
                float v0 = (a0.x * a1.x) * a2.x;
                float v1 = (a0.y * a1.y) * a2.y;
                uint32_t h2 = cvt2bf(v1, v0);
                float e0 = __uint_as_float(h2 << 16);
                float e1 = __uint_as_float(h2 & 0xffff0000u);
                uint32_t l2 = cvt2bf(v1 - e1, v0 - e0);
                *reinterpret_cast<uint32_t*>(ah + ip * 4) = h2;
                *reinterpret_cast<uint32_t*>(al + ip * 4) = l2;
            }
        } else {                 // rare straddle: per-element
            for (int i = lane; i < DD; i += 32) {
                const uint32_t f = flat0 + i;
                const uint32_t t = __ldg(g_tab + (f >> CSH));
                const uint32_t c = f & CMSK;
                float v = (__ldg(mono_ptr(X, t & 0xffu) + c) *
                           __ldg(mono_ptr(X, (t >> 8) & 0xffu) + c)) *
                          __ldg(mono_ptr(X, (t >> 16) & 0xffu) + c);
                __nv_bfloat16 vh = __float2bfloat16(v);
                __nv_bfloat16 vl = __float2bfloat16(v - __bfloat162float(vh));
                *reinterpret_cast<__nv_bfloat16*>(ah + i * 2) = vh;
                *reinterpret_cast<__nv_bfloat16*>(al + i * 2) = vl;
            }
        }
        if (lane < 2) {          // zero pad i = 286, 287 (last float slot)
            *reinterpret_cast<uint32_t*>(ah + 572) = 0u;
            *reinterpret_cast<uint32_t*>(al + 572) = 0u;
        }
    }
    __syncthreads();

    // ldmatrix addressing: A fragment rows 16*wr..+15; B rows 16h..16h+15.
    const uint32_t aRow = smb + SM_AH + (wr * 16 + (lane & 15)) * ROWB +
                          (lane >> 4) * 16;
    const uint32_t bOff = (h * 16 + ((lane >> 4) & 1) * 8 + (lane & 7)) * ROWB +
                          ((lane >> 3) & 1) * 16;

    float out0 = 0.f, out1 = 0.f;
    const int r0 = wr * 16 + (lane >> 2);      // C rows r0, r0+8
    const uint32_t qh0 = smb + SM_AH + r0 * ROWB + (lane & 3) * 4;
    const uint32_t ql0 = smb + SM_AL + r0 * ROWB + (lane & 3) * 4;

    for (int c = 0; c < NCH; c++) {
        const int b = c & 1;
        if (tid == 0 && c + 1 < NCH) {
            const int b2 = (c + 1) & 1;
            if (c >= 1)
                mbar_wait(smb + SM_EMPTY0 + 8 * b2, ((c - 1) >> 1) & 1);
            mbar_expect(smb + SM_FULL0 + 8 * b2, CHB);
            bulk_g2s(smb + SM_B + b2 * CHB,
                     reinterpret_cast<const char*>(g_B) + (size_t)(c + 1) * CHB,
                     CHB, smb + SM_FULL0 + 8 * b2);
        }
        mbar_wait(smb + SM_FULL0 + 8 * b, (c >> 1) & 1);

        const uint32_t bh = smb + SM_B + b * CHB + bOff;
        const uint32_t bl = bh + NB * ROWB;

        // 6 independent accumulators: C[product(3)][n8 group(2)]
        float C[3][2][4];
#pragma unroll
        for (int p = 0; p < 3; p++)
#pragma unroll
            for (int g = 0; g < 2; g++)
#pragma unroll
                for (int u = 0; u < 4; u++) C[p][g][u] = 0.f;

        const int kmax = 2 * c + 2;    // triangular: S[k][n]=0 for k>n

        uint32_t fah[2][4], fal[2][4], fh[2][4], fl[2][4];
        ldsm4(fah[0], aRow);
        ldsm4(fal[0], aRow + (SM_AL - SM_AH));
        ldsm4(fh[0], bh);
        ldsm4(fl[0], bl);

#pragma unroll 2
        for (int k = 0; k < kmax; k++) {
            const int cur = k & 1, nxt = cur ^ 1;
            if (k + 1 < kmax) {
                const uint32_t ko = (k + 1) * 32;
                ldsm4(fah[nxt], aRow + ko);
                ldsm4(fal[nxt], aRow + (SM_AL - SM_AH) + ko);
                ldsm4(fh[nxt], bh + ko);
                ldsm4(fl[nxt], bl + ko);
            }
            mma_bf16(C[0][0], fah[cur], fh[cur][0], fh[cur][1]);
            mma_bf16(C[0][1], fah[cur], fh[cur][2], fh[cur][3]);
            mma_bf16(C[1][0], fah[cur], fl[cur][0], fl[cur][1]);
            mma_bf16(C[1][1], fah[cur], fl[cur][2], fl[cur][3]);
            mma_bf16(C[2][0], fal[cur], fh[cur][0], fh[cur][1]);
            mma_bf16(C[2][1], fal[cur], fh[cur][2], fh[cur][3]);
        }
        mbar_arrive(smb + SM_EMPTY0 + 8 * b);

        // ---- Fused epilogue: out += (C0+C1+C2) ∘ q over this warp's 16 cols
        const int jb = c * 32 + h * 16;
#pragma unroll
        for (int nc = 0; nc < 2; nc++) {
            const uint32_t jo = (jb + nc * 8) * 2;
            uint32_t vh, vl, wh, wl;
            asm volatile("ld.shared.b32 %0, [%1];" : "=r"(vh) : "r"(qh0 + jo));
            asm volatile("ld.shared.b32 %0, [%1];" : "=r"(vl) : "r"(ql0 + jo));
            asm volatile("ld.shared.b32 %0, [%1];" : "=r"(wh)
                         : "r"(qh0 + 8 * ROWB + jo));
            asm volatile("ld.shared.b32 %0, [%1];" : "=r"(wl)
                         : "r"(ql0 + 8 * ROWB + jo));
            float qe = __uint_as_float(vh << 16) + __uint_as_float(vl << 16);
            float qo = __uint_as_float(vh & 0xffff0000u) +
                       __uint_as_float(vl & 0xffff0000u);
            float re = __uint_as_float(wh << 16) + __uint_as_float(wl << 16);
            float ro = __uint_as_float(wh & 0xffff0000u) +
                       __uint_as_float(wl & 0xffff0000u);
            float t0 = C[0][nc][0] + C[1][nc][0] + C[2][nc][0];
            float t1 = C[0][nc][1] + C[1][nc][1] + C[2][nc][1];
            float t2 = C[0][nc][2] + C[1][nc][2] + C[2][nc][2];
            float t3 = C[0][nc][3] + C[1][nc][3] + C[2][nc][3];
            out0 = fmaf(t0, qe, out0);
            out0 = fmaf(t1, qo, out0);
            out1 = fmaf(t2, re, out1);
            out1 = fmaf(t3, ro, out1);
        }
    }

    // Reduce the 4 j-phases within lane quads.
    out0 += __shfl_xor_sync(0xffffffffu, out0, 1);
    out0 += __shfl_xor_sync(0xffffffffu, out0, 2);
    out1 += __shfl_xor_sync(0xffffffffu, out1, 1);
    out1 += __shfl_xor_sync(0xffffffffu, out1, 2);

    // Combine the two N-halves via smem partials.
    float* SR = reinterpret_cast<float*>(sm + SM_SR);
    if ((lane & 3) == 0) {
        SR[h * BM + r0]     = out0;
        SR[h * BM + r0 + 8] = out1;
    }
    __syncthreads();
    if (tid < BM)
        out[blockIdx.x * BM + tid] = SR[tid] + SR[BM + tid];
}

// ---------------------------------------------------------------------------
// Launch
// ---------------------------------------------------------------------------
extern "C" void kernel_launch(void* const* d_in, const int* in_sizes, int n_in,
                              void* d_out, int out_size) {
    const float* X = (const float*)d_in[0];   // x flat (xr[k][c] = X[k*NPTS+c])
    const float* M = (const float*)d_in[1];   // M_inv 286x286
    float* out = (float*)d_out;

    k_prep<<<NPTS / 256, 256>>>(M);

    cudaFuncSetAttribute(k_main, cudaFuncAttributeMaxDynamicSharedMemorySize,
                         SMEM_TOTAL);
    k_main<<<NPTS / BM, THREADS, SMEM_TOTAL>>>(X, out);
}

// round 12
// speedup vs baseline: 2.1189x; 1.1740x over previous
#include <cuda_runtime.h>
#include <cuda_fp16.h>
#include <cstdint>

#define NPTS 262144         // 2^18 points
#define CSH  18             // log2(NPTS)
#define CMSK 0x3FFFFu
#define DIMS 10
#define DD   286            // comb(13,3)
#define KT   288            // K padded: 18 ksteps of 16
#define ROWE 296            // A/B row stride in fp16 elems (592 B)
#define ROWB 592            // row stride bytes
#define NB   32             // N columns per streamed B chunk
#define NCH  9              // 288 / 32 chunks
#define CHB  (NB * ROWB)    // bytes per chunk (single fp16 image) = 18944
#define BM   128
#define THREADS 512
#define ONEI 10             // sentinel index -> ones row

typedef unsigned long long ull;

// B image of symmetrized upper-tri S (S[k][n] = k<n: M[k][n]+M[n][k];
// k==n: M[n][n]; else 0), single fp16, layout [chunk 9][32 rows x 592 B].
__device__ uint4 g_B[NCH * CHB / 16];
__device__ float g_ones[NPTS];
// Monomial index table, reference _exponent_nk order: i0 | i1<<8 | i2<<16.
__device__ uint32_t g_tab[DD];

// ---------------------------------------------------------------------------
// k_prep: B image + ones row + monomial table.
// ---------------------------------------------------------------------------
__global__ void k_prep(const float* __restrict__ M) {
    int idx = blockIdx.x * blockDim.x + threadIdx.x;
    if (idx < NPTS) g_ones[idx] = 1.0f;
    if (idx < KT * KT) {
        int n = idx / KT, k = idx - n * KT;
        float v = 0.0f;
        if (n < DD && k < DD) {
            if (k < n)       v = M[k * DD + n] + M[n * DD + k];
            else if (k == n) v = M[n * DD + n];
        }
        __half* B = reinterpret_cast<__half*>(g_B);
        size_t cb = (size_t)(n >> 5) * (CHB / 2);
        B[cb + (size_t)(n & 31) * ROWE + k] = __float2half_rn(v);
    }
    if (idx == 0) {
        int r = 0;
        g_tab[r++] = ONEI | (ONEI << 8) | (ONEI << 16);
        for (int j = 0; j < DIMS; j++)
            g_tab[r++] = j | (ONEI << 8) | (ONEI << 16);
        for (int j = 0; j < DIMS; j++)
            for (int a = j; a < DIMS; a++)
                g_tab[r++] = j | (a << 8) | (ONEI << 16);
        for (int j = 0; j < DIMS; j++)
            for (int a = j; a < DIMS; a++)
                for (int b = a; b < DIMS; b++)
                    g_tab[r++] = j | (a << 8) | (b << 16);
    }
}

// ---------------------------------------------------------------------------
// Base-ISA PTX helpers.
// ---------------------------------------------------------------------------
__device__ __forceinline__ void ldsm4(uint32_t r[4], uint32_t addr) {
    asm volatile(
        "ldmatrix.sync.aligned.m8n8.x4.shared.b16 {%0,%1,%2,%3}, [%4];"
        : "=r"(r[0]), "=r"(r[1]), "=r"(r[2]), "=r"(r[3]) : "r"(addr));
}
__device__ __forceinline__ void mma_f16(float c[4], const uint32_t a[4],
                                        uint32_t b0, uint32_t b1) {
    asm volatile(
        "mma.sync.aligned.m16n8k16.row.col.f32.f16.f16.f32 "
        "{%0,%1,%2,%3}, {%4,%5,%6,%7}, {%8,%9}, {%0,%1,%2,%3};"
        : "+f"(c[0]), "+f"(c[1]), "+f"(c[2]), "+f"(c[3])
        : "r"(a[0]), "r"(a[1]), "r"(a[2]), "r"(a[3]), "r"(b0), "r"(b1));
}
__device__ __forceinline__ void bulk_g2s(uint32_t dst, const void* src,
                                         uint32_t bytes, uint32_t mbar) {
    asm volatile(
        "cp.async.bulk.shared::cta.global.mbarrier::complete_tx::bytes "
        "[%0], [%1], %2, [%3];"
        :: "r"(dst), "l"(src), "r"(bytes), "r"(mbar) : "memory");
}
__device__ __forceinline__ void mbar_init(uint32_t mbar, uint32_t cnt) {
    asm volatile("mbarrier.init.shared.b64 [%0], %1;" :: "r"(mbar), "r"(cnt)
                 : "memory");
}
__device__ __forceinline__ void mbar_expect(uint32_t mbar, uint32_t bytes) {
    asm volatile("mbarrier.arrive.expect_tx.shared.b64 _, [%0], %1;"
                 :: "r"(mbar), "r"(bytes) : "memory");
}
__device__ __forceinline__ void mbar_arrive(uint32_t mbar) {
    asm volatile("mbarrier.arrive.shared.b64 _, [%0];" :: "r"(mbar)
                 : "memory");
}
__device__ __forceinline__ void mbar_wait(uint32_t mbar, uint32_t parity) {
    asm volatile(
        "{\n\t.reg .pred P1;\n\t"
        "W_%=:\n\t"
        "mbarrier.try_wait.parity.acquire.cta.shared::cta.b64 P1, [%0], %1, 0x989680;\n\t"
        "@P1 bra.uni D_%=;\n\t"
        "bra.uni W_%=;\n\t"
        "D_%=:\n\t}"
        :: "r"(mbar), "r"(parity) : "memory");
}
__device__ __forceinline__ const float* mono_ptr(const float* X, uint32_t i) {
    return (i < DIMS) ? (X + (size_t)i * NPTS) : g_ones;
}
__device__ __forceinline__ float2 up2(uint32_t u) {   // 2 packed fp16 -> f32
    __half2 h = *reinterpret_cast<__half2*>(&u);
    return __half22float2(h);
}

// SMEM map
constexpr int SM_FULL0 = 0, SM_EMPTY0 = 16;
constexpr int SM_SR = 32;                      // [2][BM] partial sums (1 KB)
constexpr int SM_AH = 1056;
constexpr int SM_AL = SM_AH + BM * ROWB;       // 76832
constexpr int SM_B  = SM_AL + BM * ROWB;       // 152608 (16B aligned)
constexpr int SMEM_TOTAL = SM_B + 2 * CHB;     // 190496

// ---------------------------------------------------------------------------
// k_main: direct A build (fp16 hi/lo split of exact fp32 monomials) ->
// double-buffered single-fp16 B stream + triangular 2-product HMMA GEMM,
// 16 warps (8 row-groups x 2 N-halves), fused T·q epilogue.
// ---------------------------------------------------------------------------
__global__ __launch_bounds__(THREADS, 1) void k_main(
        const float* __restrict__ X, float* __restrict__ out) {
    extern __shared__ char sm[];
    const uint32_t smb = (uint32_t)__cvta_generic_to_shared(sm);
    const int tid = threadIdx.x, w = tid >> 5, lane = tid & 31;
    const int wr = w >> 1;         // row group 0..7 (rows 16*wr..16*wr+15)
    const int h  = w & 1;          // N half 0/1 (chunk cols 16h..16h+15)

    if (tid == 0) {
        mbar_init(smb + SM_FULL0, 1);
        mbar_init(smb + SM_FULL0 + 8, 1);
        mbar_init(smb + SM_EMPTY0, THREADS);
        mbar_init(smb + SM_EMPTY0 + 8, THREADS);
    }
    __syncthreads();
    if (tid == 0) {    // kick chunk 0 copy; overlaps A build
        mbar_expect(smb + SM_FULL0, CHB);
        bulk_g2s(smb + SM_B, g_B, CHB, smb + SM_FULL0);
    }

    // ---- A build: warp w builds 8 rows directly from L2-resident x ----
#pragma unroll
    for (int rr = 0; rr < 8; rr++) {
        const int row = w * 8 + rr;
        const int n = blockIdx.x * BM + row;
        const uint32_t flat0 = (uint32_t)n * (uint32_t)DD;
        char* ah = sm + SM_AH + row * ROWB;
        char* al = sm + SM_AL + row * ROWB;
        const uint32_t c0 = flat0 & CMSK;      // even (286 even)
        if (c0 + DD <= NPTS) {   // fast path: one monomial, contiguous window
            const uint32_t t = __ldg(g_tab + (flat0 >> CSH));
            const float* p0 = mono_ptr(X, t & 0xffu) + c0;
            const float* p1 = mono_ptr(X, (t >> 8) & 0xffu) + c0;
            const float* p2 = mono_ptr(X, (t >> 16) & 0xffu) + c0;
            for (int ip = lane; ip < 143; ip += 32) {   // 143 f32 pairs
                float2 a0 = *reinterpret_cast<const float2*>(p0 + 2 * ip);
                float2 a1 = *reinterpret_cast<const float2*>(p1 + 2 * ip);
                float2 a2 = *reinterpret_cast<const float2*>(p2 + 2 * ip);
                float v0 = (a0.x * a1.x) * a2.x;
                float v1 = (a0.y * a1.y) * a2.y;
                __half h0 = __float2half_rn(v0);
                __half h1 = __float2half_rn(v1);
                __half l0 = __float2half_rn(v0 - __half2float(h0));
                __half l1 = __float2half_rn(v1 - __half2float(h1));
                __half2 hp = __halves2half2(h0, h1);
                __half2 lp = __halves2half2(l0, l1);
                *reinterpret_cast<__half2*>(ah + ip * 4) = hp;
                *reinterpret_cast<__half2*>(al + ip * 4) = lp;
            }
        } else {                 // rare straddle: per-element
            for (int i = lane; i < DD; i += 32) {
                const uint32_t f = flat0 + i;
                const uint32_t t = __ldg(g_tab + (f >> CSH));
                const uint32_t c = f & CMSK;
                float v = (__ldg(mono_ptr(X, t & 0xffu) + c) *
                           __ldg(mono_ptr(X, (t >> 8) & 0xffu) + c)) *
                          __ldg(mono_ptr(X, (t >> 16) & 0xffu) + c);
                __half vh = __float2half_rn(v);
                __half vl = __float2half_rn(v - __half2float(vh));
                *reinterpret_cast<__half*>(ah + i * 2) = vh;
                *reinterpret_cast<__half*>(al + i * 2) = vl;
            }
        }
        if (lane < 2) {          // zero pad i = 286, 287
            *reinterpret_cast<uint32_t*>(ah + 572) = 0u;
            *reinterpret_cast<uint32_t*>(al + 572) = 0u;
        }
    }
    __syncthreads();

    // ldmatrix addressing: A rows 16*wr..+15; B rows 16h..16h+15.
    const uint32_t aRow = smb + SM_AH + (wr * 16 + (lane & 15)) * ROWB +
                          (lane >> 4) * 16;
    const uint32_t bOff = (h * 16 + ((lane >> 4) & 1) * 8 + (lane & 7)) * ROWB +
                          ((lane >> 3) & 1) * 16;

    float out0 = 0.f, out1 = 0.f;
    const int r0 = wr * 16 + (lane >> 2);      // C rows r0, r0+8
    const uint32_t qh0 = smb + SM_AH + r0 * ROWB + (lane & 3) * 4;
    const uint32_t ql0 = smb + SM_AL + r0 * ROWB + (lane & 3) * 4;

    for (int c = 0; c < NCH; c++) {
        const int b = c & 1;
        if (tid == 0 && c + 1 < NCH) {
            const int b2 = (c + 1) & 1;
            if (c >= 1)
                mbar_wait(smb + SM_EMPTY0 + 8 * b2, ((c - 1) >> 1) & 1);
            mbar_expect(smb + SM_FULL0 + 8 * b2, CHB);
            bulk_g2s(smb + SM_B + b2 * CHB,
                     reinterpret_cast<const char*>(g_B) + (size_t)(c + 1) * CHB,
                     CHB, smb + SM_FULL0 + 8 * b2);
        }
        mbar_wait(smb + SM_FULL0 + 8 * b, (c >> 1) & 1);

        const uint32_t bm = smb + SM_B + b * CHB + bOff;

        // 4 independent accumulators: C[product(2)][n8 group(2)]
        float C[2][2][4];
#pragma unroll
        for (int p = 0; p < 2; p++)
#pragma unroll
            for (int g = 0; g < 2; g++)
#pragma unroll
                for (int u = 0; u < 4; u++) C[p][g][u] = 0.f;

        const int kmax = 2 * c + 2;    // triangular: S[k][n]=0 for k>n

        uint32_t fah[2][4], fal[2][4], fm[2][4];
        ldsm4(fah[0], aRow);
        ldsm4(fal[0], aRow + (SM_AL - SM_AH));
        ldsm4(fm[0], bm);

#pragma unroll 2
        for (int k = 0; k < kmax; k++) {
            const int cur = k & 1, nxt = cur ^ 1;
            if (k + 1 < kmax) {
                const uint32_t ko = (k + 1) * 32;
                ldsm4(fah[nxt], aRow + ko);
                ldsm4(fal[nxt], aRow + (SM_AL - SM_AH) + ko);
                ldsm4(fm[nxt], bm + ko);
            }
            mma_f16(C[0][0], fah[cur], fm[cur][0], fm[cur][1]);
            mma_f16(C[0][1], fah[cur], fm[cur][2], fm[cur][3]);
            mma_f16(C[1][0], fal[cur], fm[cur][0], fm[cur][1]);
            mma_f16(C[1][1], fal[cur], fm[cur][2], fm[cur][3]);
        }
        mbar_arrive(smb + SM_EMPTY0 + 8 * b);

        // ---- Fused epilogue: out += (C0+C1) ∘ q over this warp's 16 cols
        const int jb = c * 32 + h * 16;
#pragma unroll
        for (int nc = 0; nc < 2; nc++) {
            const uint32_t jo = (jb + nc * 8) * 2;
            uint32_t vh, vl, wh, wl;
            asm volatile("ld.shared.b32 %0, [%1];" : "=r"(vh) : "r"(qh0 + jo));
            asm volatile("ld.shared.b32 %0, [%1];" : "=r"(vl) : "r"(ql0 + jo));
            asm volatile("ld.shared.b32 %0, [%1];" : "=r"(wh)
                         : "r"(qh0 + 8 * ROWB + jo));
            asm volatile("ld.shared.b32 %0, [%1];" : "=r"(wl)
                         : "r"(ql0 + 8 * ROWB + jo));
            float2 vhf = up2(vh), vlf = up2(vl), whf = up2(wh), wlf = up2(wl);
            float qe = vhf.x + vlf.x, qo = vhf.y + vlf.y;
            float re = whf.x + wlf.x, ro = whf.y + wlf.y;
            float t0 = C[0][nc][0] + C[1][nc][0];
            float t1 = C[0][nc][1] + C[1][nc][1];
            float t2 = C[0][nc][2] + C[1][nc][2];
            float t3 = C[0][nc][3] + C[1][nc][3];
            out0 = fmaf(t0, qe, out0);
            out0 = fmaf(t1, qo, out0);
            out1 = fmaf(t2, re, out1);
            out1 = fmaf(t3, ro, out1);
        }
    }

    // Reduce the 4 j-phases within lane quads.
    out0 += __shfl_xor_sync(0xffffffffu, out0, 1);
    out0 += __shfl_xor_sync(0xffffffffu, out0, 2);
    out1 += __shfl_xor_sync(0xffffffffu, out1, 1);
    out1 += __shfl_xor_sync(0xffffffffu, out1, 2);

    // Combine the two N-halves via smem partials.
    float* SR = reinterpret_cast<float*>(sm + SM_SR);
    if ((lane & 3) == 0) {
        SR[h * BM + r0]     = out0;
        SR[h * BM + r0 + 8] = out1;
    }
    __syncthreads();
    if (tid < BM)
        out[blockIdx.x * BM + tid] = SR[tid] + SR[BM + tid];
}

// ---------------------------------------------------------------------------
// Launch
// ---------------------------------------------------------------------------
extern "C" void kernel_launch(void* const* d_in, const int* in_sizes, int n_in,
                              void* d_out, int out_size) {
    const float* X = (const float*)d_in[0];   // x flat (xr[k][c] = X[k*NPTS+c])
    const float* M = (const float*)d_in[1];   // M_inv 286x286
    float* out = (float*)d_out;

    k_prep<<<NPTS / 256, 256>>>(M);

    cudaFuncSetAttribute(k_main, cudaFuncAttributeMaxDynamicSharedMemorySize,
                         SMEM_TOTAL);
    k_main<<<NPTS / BM, THREADS, SMEM_TOTAL>>>(X, out);
}

// round 13
// speedup vs baseline: 2.4981x; 1.1790x over previous
#include <cuda_runtime.h>
#include <cuda_fp16.h>
#include <cstdint>

#define NPTS 262144         // 2^18 points
#define CSH  18             // log2(NPTS)
#define CMSK 0x3FFFFu
#define DIMS 10
#define DD   286            // comb(13,3)
#define KT   288            // K padded: 18 ksteps of 16
#define ROWE 296            // A/B row stride in fp16 elems (592 B)
#define ROWB 592            // row stride bytes
#define NB   32             // N columns per streamed B chunk
#define NCH  9              // 288 / 32 chunks
#define CHB  (NB * ROWB)    // bytes per chunk (single fp16 image) = 18944
#define BM   128
#define THREADS 512
#define ONEI 10             // sentinel index -> ones row

typedef unsigned long long ull;

// B image of symmetrized upper-tri S (S[k][n] = k<n: M[k][n]+M[n][k];
// k==n: M[n][n]; else 0), single fp16, layout [chunk 9][32 rows x 592 B].
__device__ uint4 g_B[NCH * CHB / 16];
__device__ float g_ones[NPTS];
// Monomial index table, reference _exponent_nk order: i0 | i1<<8 | i2<<16.
__device__ uint32_t g_tab[DD];

// ---------------------------------------------------------------------------
// k_prep: B image + ones row + monomial table.
// ---------------------------------------------------------------------------
__global__ void k_prep(const float* __restrict__ M) {
    int idx = blockIdx.x * blockDim.x + threadIdx.x;
    if (idx < NPTS) g_ones[idx] = 1.0f;
    if (idx < KT * KT) {
        int n = idx / KT, k = idx - n * KT;
        float v = 0.0f;
        if (n < DD && k < DD) {
            if (k < n)       v = M[k * DD + n] + M[n * DD + k];
            else if (k == n) v = M[n * DD + n];
        }
        __half* B = reinterpret_cast<__half*>(g_B);
        size_t cb = (size_t)(n >> 5) * (CHB / 2);
        B[cb + (size_t)(n & 31) * ROWE + k] = __float2half_rn(v);
    }
    if (idx == 0) {
        int r = 0;
        g_tab[r++] = ONEI | (ONEI << 8) | (ONEI << 16);
        for (int j = 0; j < DIMS; j++)
            g_tab[r++] = j | (ONEI << 8) | (ONEI << 16);
        for (int j = 0; j < DIMS; j++)
            for (int a = j; a < DIMS; a++)
                g_tab[r++] = j | (a << 8) | (ONEI << 16);
        for (int j = 0; j < DIMS; j++)
            for (int a = j; a < DIMS; a++)
                for (int b = a; b < DIMS; b++)
                    g_tab[r++] = j | (a << 8) | (b << 16);
    }
}

// ---------------------------------------------------------------------------
// Base-ISA PTX helpers.
// ---------------------------------------------------------------------------
__device__ __forceinline__ void ldsm4(uint32_t r[4], uint32_t addr) {
    asm volatile(
        "ldmatrix.sync.aligned.m8n8.x4.shared.b16 {%0,%1,%2,%3}, [%4];"
        : "=r"(r[0]), "=r"(r[1]), "=r"(r[2]), "=r"(r[3]) : "r"(addr));
}
__device__ __forceinline__ void mma_f16(float c[4], const uint32_t a[4],
                                        uint32_t b0, uint32_t b1) {
    asm volatile(
        "mma.sync.aligned.m16n8k16.row.col.f32.f16.f16.f32 "
        "{%0,%1,%2,%3}, {%4,%5,%6,%7}, {%8,%9}, {%0,%1,%2,%3};"
        : "+f"(c[0]), "+f"(c[1]), "+f"(c[2]), "+f"(c[3])
        : "r"(a[0]), "r"(a[1]), "r"(a[2]), "r"(a[3]), "r"(b0), "r"(b1));
}
__device__ __forceinline__ void bulk_g2s(uint32_t dst, const void* src,
                                         uint32_t bytes, uint32_t mbar) {
    asm volatile(
        "cp.async.bulk.shared::cta.global.mbarrier::complete_tx::bytes "
        "[%0], [%1], %2, [%3];"
        :: "r"(dst), "l"(src), "r"(bytes), "r"(mbar) : "memory");
}
__device__ __forceinline__ void mbar_init(uint32_t mbar, uint32_t cnt) {
    asm volatile("mbarrier.init.shared.b64 [%0], %1;" :: "r"(mbar), "r"(cnt)
                 : "memory");
}
__device__ __forceinline__ void mbar_expect(uint32_t mbar, uint32_t bytes) {
    asm volatile("mbarrier.arrive.expect_tx.shared.b64 _, [%0], %1;"
                 :: "r"(mbar), "r"(bytes) : "memory");
}
__device__ __forceinline__ void mbar_arrive(uint32_t mbar) {
    asm volatile("mbarrier.arrive.shared.b64 _, [%0];" :: "r"(mbar)
                 : "memory");
}
__device__ __forceinline__ void mbar_wait(uint32_t mbar, uint32_t parity) {
    asm volatile(
        "{\n\t.reg .pred P1;\n\t"
        "W_%=:\n\t"
        "mbarrier.try_wait.parity.acquire.cta.shared::cta.b64 P1, [%0], %1, 0x989680;\n\t"
        "@P1 bra.uni D_%=;\n\t"
        "bra.uni W_%=;\n\t"
        "D_%=:\n\t}"
        :: "r"(mbar), "r"(parity) : "memory");
}
__device__ __forceinline__ const float* mono_ptr(const float* X, uint32_t i) {
    return (i < DIMS) ? (X + (size_t)i * NPTS) : g_ones;
}
__device__ __forceinline__ float2 up2(uint32_t u) {   // 2 packed fp16 -> f32
    __half2 h = *reinterpret_cast<__half2*>(&u);
    return __half22float2(h);
}

// SMEM map
constexpr int SM_FULL0 = 0, SM_EMPTY0 = 16;
constexpr int SM_SR = 32;                      // [2][BM] partial sums (1 KB)
constexpr int SM_AH = 1056;
constexpr int SM_AL = SM_AH + BM * ROWB;       // 76832 (epilogue-only q_lo)
constexpr int SM_B  = SM_AL + BM * ROWB;       // 152608 (16B aligned)
constexpr int SMEM_TOTAL = SM_B + 2 * CHB;     // 190496

// ---------------------------------------------------------------------------
// k_main: direct A build (fp16 hi/lo split of exact fp32 monomials; lo kept
// ONLY for exact q in the epilogue) -> double-buffered single-fp16 B stream +
// triangular SINGLE-product HMMA GEMM, 16 warps (8 row-groups x 2 N-halves),
// fused T·q epilogue with exact q = qh + ql.
// ---------------------------------------------------------------------------
__global__ __launch_bounds__(THREADS, 1) void k_main(
        const float* __restrict__ X, float* __restrict__ out) {
    extern __shared__ char sm[];
    const uint32_t smb = (uint32_t)__cvta_generic_to_shared(sm);
    const int tid = threadIdx.x, w = tid >> 5, lane = tid & 31;
    const int wr = w >> 1;         // row group 0..7 (rows 16*wr..16*wr+15)
    const int h  = w & 1;          // N half 0/1 (chunk cols 16h..16h+15)

    if (tid == 0) {
        mbar_init(smb + SM_FULL0, 1);
        mbar_init(smb + SM_FULL0 + 8, 1);
        mbar_init(smb + SM_EMPTY0, THREADS);
        mbar_init(smb + SM_EMPTY0 + 8, THREADS);
    }
    __syncthreads();
    if (tid == 0) {    // kick chunk 0 copy; overlaps A build
        mbar_expect(smb + SM_FULL0, CHB);
        bulk_g2s(smb + SM_B, g_B, CHB, smb + SM_FULL0);
    }

    // ---- A build: warp w builds 8 rows directly from L2-resident x ----
#pragma unroll
    for (int rr = 0; rr < 8; rr++) {
        const int row = w * 8 + rr;
        const int n = blockIdx.x * BM + row;
        const uint32_t flat0 = (uint32_t)n * (uint32_t)DD;
        char* ah = sm + SM_AH + row * ROWB;
        char* al = sm + SM_AL + row * ROWB;
        const uint32_t c0 = flat0 & CMSK;      // even (286 even)
        if (c0 + DD <= NPTS) {   // fast path: one monomial, contiguous window
            const uint32_t t = __ldg(g_tab + (flat0 >> CSH));
            const float* p0 = mono_ptr(X, t & 0xffu) + c0;
            const float* p1 = mono_ptr(X, (t >> 8) & 0xffu) + c0;
            const float* p2 = mono_ptr(X, (t >> 16) & 0xffu) + c0;
            for (int ip = lane; ip < 143; ip += 32) {   // 143 f32 pairs
                float2 a0 = *reinterpret_cast<const float2*>(p0 + 2 * ip);
                float2 a1 = *reinterpret_cast<const float2*>(p1 + 2 * ip);
                float2 a2 = *reinterpret_cast<const float2*>(p2 + 2 * ip);
                float v0 = (a0.x * a1.x) * a2.x;
                float v1 = (a0.y * a1.y) * a2.y;
                __half h0 = __float2half_rn(v0);
                __half h1 = __float2half_rn(v1);
                __half l0 = __float2half_rn(v0 - __half2float(h0));
                __half l1 = __float2half_rn(v1 - __half2float(h1));
                *reinterpret_cast<__half2*>(ah + ip * 4) = __halves2half2(h0, h1);
                *reinterpret_cast<__half2*>(al + ip * 4) = __halves2half2(l0, l1);
            }
        } else {                 // rare straddle: per-element
            for (int i = lane; i < DD; i += 32) {
                const uint32_t f = flat0 + i;
                const uint32_t t = __ldg(g_tab + (f >> CSH));
                const uint32_t c = f & CMSK;
                float v = (__ldg(mono_ptr(X, t & 0xffu) + c) *
                           __ldg(mono_ptr(X, (t >> 8) & 0xffu) + c)) *
                          __ldg(mono_ptr(X, (t >> 16) & 0xffu) + c);
                __half vh = __float2half_rn(v);
                __half vl = __float2half_rn(v - __half2float(vh));
                *reinterpret_cast<__half*>(ah + i * 2) = vh;
                *reinterpret_cast<__half*>(al + i * 2) = vl;
            }
        }
        if (lane < 2) {          // zero pad i = 286, 287
            *reinterpret_cast<uint32_t*>(ah + 572) = 0u;
            *reinterpret_cast<uint32_t*>(al + 572) = 0u;
        }
    }
    __syncthreads();

    // ldmatrix addressing: A rows 16*wr..+15; B rows 16h..16h+15.
    const uint32_t aRow = smb + SM_AH + (wr * 16 + (lane & 15)) * ROWB +
                          (lane >> 4) * 16;
    const uint32_t bOff = (h * 16 + ((lane >> 4) & 1) * 8 + (lane & 7)) * ROWB +
                          ((lane >> 3) & 1) * 16;

    float out0 = 0.f, out1 = 0.f;
    const int r0 = wr * 16 + (lane >> 2);      // C rows r0, r0+8
    const uint32_t qh0 = smb + SM_AH + r0 * ROWB + (lane & 3) * 4;
    const uint32_t ql0 = smb + SM_AL + r0 * ROWB + (lane & 3) * 4;

    for (int c = 0; c < NCH; c++) {
        const int b = c & 1;
        if (tid == 0 && c + 1 < NCH) {
            const int b2 = (c + 1) & 1;
            if (c >= 1)
                mbar_wait(smb + SM_EMPTY0 + 8 * b2, ((c - 1) >> 1) & 1);
            mbar_expect(smb + SM_FULL0 + 8 * b2, CHB);
            bulk_g2s(smb + SM_B + b2 * CHB,
                     reinterpret_cast<const char*>(g_B) + (size_t)(c + 1) * CHB,
                     CHB, smb + SM_FULL0 + 8 * b2);
        }
        mbar_wait(smb + SM_FULL0 + 8 * b, (c >> 1) & 1);

        const uint32_t bm = smb + SM_B + b * CHB + bOff;

        // 2 independent accumulators: C[n8 group(2)], single product qh*m.
        float C[2][4];
#pragma unroll
        for (int g = 0; g < 2; g++)
#pragma unroll
            for (int u = 0; u < 4; u++) C[g][u] = 0.f;

        const int kmax = 2 * c + 2;    // triangular: S[k][n]=0 for k>n

        uint32_t fah[2][4], fm[2][4];
        ldsm4(fah[0], aRow);
        ldsm4(fm[0], bm);

#pragma unroll 2
        for (int k = 0; k < kmax; k++) {
            const int cur = k & 1, nxt = cur ^ 1;
            if (k + 1 < kmax) {
                const uint32_t ko = (k + 1) * 32;
                ldsm4(fah[nxt], aRow + ko);
                ldsm4(fm[nxt], bm + ko);
            }
            mma_f16(C[0], fah[cur], fm[cur][0], fm[cur][1]);
            mma_f16(C[1], fah[cur], fm[cur][2], fm[cur][3]);
        }
        mbar_arrive(smb + SM_EMPTY0 + 8 * b);

        // ---- Fused epilogue: out += C ∘ q (exact q = qh + ql), 16 cols ----
        const int jb = c * 32 + h * 16;
#pragma unroll
        for (int nc = 0; nc < 2; nc++) {
            const uint32_t jo = (jb + nc * 8) * 2;
            uint32_t vh, vl, wh, wl;
            asm volatile("ld.shared.b32 %0, [%1];" : "=r"(vh) : "r"(qh0 + jo));
            asm volatile("ld.shared.b32 %0, [%1];" : "=r"(vl) : "r"(ql0 + jo));
            asm volatile("ld.shared.b32 %0, [%1];" : "=r"(wh)
                         : "r"(qh0 + 8 * ROWB + jo));
            asm volatile("ld.shared.b32 %0, [%1];" : "=r"(wl)
                         : "r"(ql0 + 8 * ROWB + jo));
            float2 vhf = up2(vh), vlf = up2(vl), whf = up2(wh), wlf = up2(wl);
            float qe = vhf.x + vlf.x, qo = vhf.y + vlf.y;
            float re = whf.x + wlf.x, ro = whf.y + wlf.y;
            out0 = fmaf(C[nc][0], qe, out0);
            out0 = fmaf(C[nc][1], qo, out0);
            out1 = fmaf(C[nc][2], re, out1);
            out1 = fmaf(C[nc][3], ro, out1);
        }
    }

    // Reduce the 4 j-phases within lane quads.
    out0 += __shfl_xor_sync(0xffffffffu, out0, 1);
    out0 += __shfl_xor_sync(0xffffffffu, out0, 2);
    out1 += __shfl_xor_sync(0xffffffffu, out1, 1);
    out1 += __shfl_xor_sync(0xffffffffu, out1, 2);

    // Combine the two N-halves via smem partials.
    float* SR = reinterpret_cast<float*>(sm + SM_SR);
    if ((lane & 3) == 0) {
        SR[h * BM + r0]     = out0;
        SR[h * BM + r0 + 8] = out1;
    }
    __syncthreads();
    if (tid < BM)
        out[blockIdx.x * BM + tid] = SR[tid] + SR[BM + tid];
}

// ---------------------------------------------------------------------------
// Launch
// ---------------------------------------------------------------------------
extern "C" void kernel_launch(void* const* d_in, const int* in_sizes, int n_in,
                              void* d_out, int out_size) {
    const float* X = (const float*)d_in[0];   // x flat (xr[k][c] = X[k*NPTS+c])
    const float* M = (const float*)d_in[1];   // M_inv 286x286
    float* out = (float*)d_out;

    k_prep<<<NPTS / 256, 256>>>(M);

    cudaFuncSetAttribute(k_main, cudaFuncAttributeMaxDynamicSharedMemorySize,
                         SMEM_TOTAL);
    k_main<<<NPTS / BM, THREADS, SMEM_TOTAL>>>(X, out);
}

// round 14
// speedup vs baseline: 2.5318x; 1.0135x over previous
#include <cuda_runtime.h>
#include <cuda_fp16.h>
#include <cstdint>

#define NPTS 262144         // 2^18 points
#define CSH  18             // log2(NPTS)
#define CMSK 0x3FFFFu
#define DIMS 10
#define DD   286            // comb(13,3)
#define KT   288            // K padded: 18 ksteps of 16
#define ROWE 296            // A/B row stride in fp16 elems (592 B)
#define ROWB 592            // row stride bytes
#define NB   32             // N columns per streamed B chunk
#define NCH  9              // 288 / 32 chunks
#define CHB  (NB * ROWB)    // bytes per chunk (single fp16 image) = 18944
#define BM   64             // points per block (2 CTAs/SM)
#define THREADS 256
#define ONEI 10             // sentinel index -> ones row

typedef unsigned long long ull;

// B image of symmetrized upper-tri S (S[k][n] = k<n: M[k][n]+M[n][k];
// k==n: M[n][n]; else 0), single fp16, layout [chunk 9][32 rows x 592 B].
__device__ uint4 g_B[NCH * CHB / 16];
__device__ float g_ones[NPTS];
// Monomial index table, reference _exponent_nk order: i0 | i1<<8 | i2<<16.
__device__ uint32_t g_tab[DD];

// ---------------------------------------------------------------------------
// k_prep: B image + ones row + monomial table.
// ---------------------------------------------------------------------------
__global__ void k_prep(const float* __restrict__ M) {
    int idx = blockIdx.x * blockDim.x + threadIdx.x;
    if (idx < NPTS) g_ones[idx] = 1.0f;
    if (idx < KT * KT) {
        int n = idx / KT, k = idx - n * KT;
        float v = 0.0f;
        if (n < DD && k < DD) {
            if (k < n)       v = M[k * DD + n] + M[n * DD + k];
            else if (k == n) v = M[n * DD + n];
        }
        __half* B = reinterpret_cast<__half*>(g_B);
        size_t cb = (size_t)(n >> 5) * (CHB / 2);
        B[cb + (size_t)(n & 31) * ROWE + k] = __float2half_rn(v);
    }
    if (idx == 0) {
        int r = 0;
        g_tab[r++] = ONEI | (ONEI << 8) | (ONEI << 16);
        for (int j = 0; j < DIMS; j++)
            g_tab[r++] = j | (ONEI << 8) | (ONEI << 16);
        for (int j = 0; j < DIMS; j++)
            for (int a = j; a < DIMS; a++)
                g_tab[r++] = j | (a << 8) | (ONEI << 16);
        for (int j = 0; j < DIMS; j++)
            for (int a = j; a < DIMS; a++)
                for (int b = a; b < DIMS; b++)
                    g_tab[r++] = j | (a << 8) | (b << 16);
    }
}

// ---------------------------------------------------------------------------
// Base-ISA PTX helpers.
// ---------------------------------------------------------------------------
__device__ __forceinline__ void ldsm4(uint32_t r[4], uint32_t addr) {
    asm volatile(
        "ldmatrix.sync.aligned.m8n8.x4.shared.b16 {%0,%1,%2,%3}, [%4];"
        : "=r"(r[0]), "=r"(r[1]), "=r"(r[2]), "=r"(r[3]) : "r"(addr));
}
__device__ __forceinline__ void mma_f16(float c[4], const uint32_t a[4],
                                        uint32_t b0, uint32_t b1) {
    asm volatile(
        "mma.sync.aligned.m16n8k16.row.col.f32.f16.f16.f32 "
        "{%0,%1,%2,%3}, {%4,%5,%6,%7}, {%8,%9}, {%0,%1,%2,%3};"
        : "+f"(c[0]), "+f"(c[1]), "+f"(c[2]), "+f"(c[3])
        : "r"(a[0]), "r"(a[1]), "r"(a[2]), "r"(a[3]), "r"(b0), "r"(b1));
}
__device__ __forceinline__ void bulk_g2s(uint32_t dst, const void* src,
                                         uint32_t bytes, uint32_t mbar) {
    asm volatile(
        "cp.async.bulk.shared::cta.global.mbarrier::complete_tx::bytes "
        "[%0], [%1], %2, [%3];"
        :: "r"(dst), "l"(src), "r"(bytes), "r"(mbar) : "memory");
}
__device__ __forceinline__ void mbar_init(uint32_t mbar, uint32_t cnt) {
    asm volatile("mbarrier.init.shared.b64 [%0], %1;" :: "r"(mbar), "r"(cnt)
                 : "memory");
}
__device__ __forceinline__ void mbar_expect(uint32_t mbar, uint32_t bytes) {
    asm volatile("mbarrier.arrive.expect_tx.shared.b64 _, [%0], %1;"
                 :: "r"(mbar), "r"(bytes) : "memory");
}
__device__ __forceinline__ void mbar_arrive(uint32_t mbar) {
    asm volatile("mbarrier.arrive.shared.b64 _, [%0];" :: "r"(mbar)
                 : "memory");
}
__device__ __forceinline__ void mbar_wait(uint32_t mbar, uint32_t parity) {
    asm volatile(
        "{\n\t.reg .pred P1;\n\t"
        "W_%=:\n\t"
        "mbarrier.try_wait.parity.acquire.cta.shared::cta.b64 P1, [%0], %1, 0x989680;\n\t"
        "@P1 bra.uni D_%=;\n\t"
        "bra.uni W_%=;\n\t"
        "D_%=:\n\t}"
        :: "r"(mbar), "r"(parity) : "memory");
}
__device__ __forceinline__ const float* mono_ptr(const float* X, uint32_t i) {
    return (i < DIMS) ? (X + (size_t)i * NPTS) : g_ones;
}
__device__ __forceinline__ float2 up2(uint32_t u) {   // 2 packed fp16 -> f32
    __half2 h = *reinterpret_cast<__half2*>(&u);
    return __half22float2(h);
}

// SMEM map (per CTA; 2 CTAs/SM)
constexpr int SM_FULL0 = 0, SM_EMPTY0 = 16;
constexpr int SM_SR = 32;                      // [2][BM] partial sums (512 B)
constexpr int SM_AH = 1056;
constexpr int SM_AL = SM_AH + BM * ROWB;       // 38944 (epilogue-only q_lo)
constexpr int SM_B  = SM_AL + BM * ROWB;       // 76832 (16B aligned)
constexpr int SMEM_TOTAL = SM_B + 2 * CHB;     // 114720 (112.0 KB)

// ---------------------------------------------------------------------------
// k_main: BM=64, 8 warps, 2 CTAs/SM. Direct A build (fp16 hi/lo split of
// exact fp32 monomials; lo epilogue-only) -> double-buffered single-fp16 B
// stream + triangular single-product HMMA GEMM + fused exact-q epilogue.
// Two independent CTAs per SM overlap each other's serial phases.
// ---------------------------------------------------------------------------
__global__ __launch_bounds__(THREADS, 2) void k_main(
        const float* __restrict__ X, float* __restrict__ out) {
    extern __shared__ char sm[];
    const uint32_t smb = (uint32_t)__cvta_generic_to_shared(sm);
    const int tid = threadIdx.x, w = tid >> 5, lane = tid & 31;
    const int wr = w >> 1;         // row group 0..3 (rows 16*wr..16*wr+15)
    const int h  = w & 1;          // N half 0/1 (chunk cols 16h..16h+15)

    if (tid == 0) {
        mbar_init(smb + SM_FULL0, 1);
        mbar_init(smb + SM_FULL0 + 8, 1);
        mbar_init(smb + SM_EMPTY0, THREADS);
        mbar_init(smb + SM_EMPTY0 + 8, THREADS);
    }
    __syncthreads();
    if (tid == 0) {    // kick chunk 0 copy; overlaps A build
        mbar_expect(smb + SM_FULL0, CHB);
        bulk_g2s(smb + SM_B, g_B, CHB, smb + SM_FULL0);
    }

    // ---- A build: warp w builds 8 rows directly from L2-resident x ----
#pragma unroll
    for (int rr = 0; rr < 8; rr++) {
        const int row = w * 8 + rr;
        const int n = blockIdx.x * BM + row;
        const uint32_t flat0 = (uint32_t)n * (uint32_t)DD;
        char* ah = sm + SM_AH + row * ROWB;
        char* al = sm + SM_AL + row * ROWB;
        const uint32_t c0 = flat0 & CMSK;      // even (286 even)
        if (c0 + DD <= NPTS) {   // fast path: one monomial, contiguous window
            const uint32_t t = __ldg(g_tab + (flat0 >> CSH));
            const float* p0 = mono_ptr(X, t & 0xffu) + c0;
            const float* p1 = mono_ptr(X, (t >> 8) & 0xffu) + c0;
            const float* p2 = mono_ptr(X, (t >> 16) & 0xffu) + c0;
            for (int ip = lane; ip < 143; ip += 32) {   // 143 f32 pairs
                float2 a0 = *reinterpret_cast<const float2*>(p0 + 2 * ip);
                float2 a1 = *reinterpret_cast<const float2*>(p1 + 2 * ip);
                float2 a2 = *reinterpret_cast<const float2*>(p2 + 2 * ip);
                float v0 = (a0.x * a1.x) * a2.x;
                float v1 = (a0.y * a1.y) * a2.y;
                __half h0 = __float2half_rn(v0);
                __half h1 = __float2half_rn(v1);
                __half l0 = __float2half_rn(v0 - __half2float(h0));
                __half l1 = __float2half_rn(v1 - __half2float(h1));
                *reinterpret_cast<__half2*>(ah + ip * 4) = __halves2half2(h0, h1);
                *reinterpret_cast<__half2*>(al + ip * 4) = __halves2half2(l0, l1);
            }
        } else {                 // rare straddle: per-element
            for (int i = lane; i < DD; i += 32) {
                const uint32_t f = flat0 + i;
                const uint32_t t = __ldg(g_tab + (f >> CSH));
                const uint32_t c = f & CMSK;
                float v = (__ldg(mono_ptr(X, t & 0xffu) + c) *
                           __ldg(mono_ptr(X, (t >> 8) & 0xffu) + c)) *
                          __ldg(mono_ptr(X, (t >> 16) & 0xffu) + c);
                __half vh = __float2half_rn(v);
                __half vl = __float2half_rn(v - __half2float(vh));
                *reinterpret_cast<__half*>(ah + i * 2) = vh;
                *reinterpret_cast<__half*>(al + i * 2) = vl;
            }
        }
        if (lane < 2) {          // zero pad i = 286, 287
            *reinterpret_cast<uint32_t*>(ah + 572) = 0u;
            *reinterpret_cast<uint32_t*>(al + 572) = 0u;
        }
    }
    __syncthreads();

    // ldmatrix addressing: A rows 16*wr..+15; B rows 16h..16h+15.
    const uint32_t aRow = smb + SM_AH + (wr * 16 + (lane & 15)) * ROWB +
                          (lane >> 4) * 16;
    const uint32_t bOff = (h * 16 + ((lane >> 4) & 1) * 8 + (lane & 7)) * ROWB +
                          ((lane >> 3) & 1) * 16;

    float out0 = 0.f, out1 = 0.f;
    const int r0 = wr * 16 + (lane >> 2);      // C rows r0, r0+8
    const uint32_t qh0 = smb + SM_AH + r0 * ROWB + (lane & 3) * 4;
    const uint32_t ql0 = smb + SM_AL + r0 * ROWB + (lane & 3) * 4;

    for (int c = 0; c < NCH; c++) {
        const int b = c & 1;
        if (tid == 0 && c + 1 < NCH) {
            const int b2 = (c + 1) & 1;
            if (c >= 1)
                mbar_wait(smb + SM_EMPTY0 + 8 * b2, ((c - 1) >> 1) & 1);
            mbar_expect(smb + SM_FULL0 + 8 * b2, CHB);
            bulk_g2s(smb + SM_B + b2 * CHB,
                     reinterpret_cast<const char*>(g_B) + (size_t)(c + 1) * CHB,
                     CHB, smb + SM_FULL0 + 8 * b2);
        }
        mbar_wait(smb + SM_FULL0 + 8 * b, (c >> 1) & 1);

        const uint32_t bm = smb + SM_B + b * CHB + bOff;

        // 2 independent accumulators: C[n8 group(2)], single product qh*m.
        float C[2][4];
#pragma unroll
        for (int g = 0; g < 2; g++)
#pragma unroll
            for (int u = 0; u < 4; u++) C[g][u] = 0.f;

        const int kmax = 2 * c + 2;    // triangular: S[k][n]=0 for k>n

        uint32_t fah[2][4], fm[2][4];
        ldsm4(fah[0], aRow);
        ldsm4(fm[0], bm);

#pragma unroll 2
        for (int k = 0; k < kmax; k++) {
            const int cur = k & 1, nxt = cur ^ 1;
            if (k + 1 < kmax) {
                const uint32_t ko = (k + 1) * 32;
                ldsm4(fah[nxt], aRow + ko);
                ldsm4(fm[nxt], bm + ko);
            }
            mma_f16(C[0], fah[cur], fm[cur][0], fm[cur][1]);
            mma_f16(C[1], fah[cur], fm[cur][2], fm[cur][3]);
        }
        mbar_arrive(smb + SM_EMPTY0 + 8 * b);

        // ---- Fused epilogue: out += C ∘ q (exact q = qh + ql), 16 cols ----
        const int jb = c * 32 + h * 16;
#pragma unroll
        for (int nc = 0; nc < 2; nc++) {
            const uint32_t jo = (jb + nc * 8) * 2;
            uint32_t vh, vl, wh, wl;
            asm volatile("ld.shared.b32 %0, [%1];" : "=r"(vh) : "r"(qh0 + jo));
            asm volatile("ld.shared.b32 %0, [%1];" : "=r"(vl) : "r"(ql0 + jo));
            asm volatile("ld.shared.b32 %0, [%1];" : "=r"(wh)
                         : "r"(qh0 + 8 * ROWB + jo));
            asm volatile("ld.shared.b32 %0, [%1];" : "=r"(wl)
                         : "r"(ql0 + 8 * ROWB + jo));
            float2 vhf = up2(vh), vlf = up2(vl), whf = up2(wh), wlf = up2(wl);
            float qe = vhf.x + vlf.x, qo = vhf.y + vlf.y;
            float re = whf.x + wlf.x, ro = whf.y + wlf.y;
            out0 = fmaf(C[nc][0], qe, out0);
            out0 = fmaf(C[nc][1], qo, out0);
            out1 = fmaf(C[nc][2], re, out1);
            out1 = fmaf(C[nc][3], ro, out1);
        }
    }

    // Reduce the 4 j-phases within lane quads.
    out0 += __shfl_xor_sync(0xffffffffu, out0, 1);
    out0 += __shfl_xor_sync(0xffffffffu, out0, 2);
    out1 += __shfl_xor_sync(0xffffffffu, out1, 1);
    out1 += __shfl_xor_sync(0xffffffffu, out1, 2);

    // Combine the two N-halves via smem partials.
    float* SR = reinterpret_cast<float*>(sm + SM_SR);
    if ((lane & 3) == 0) {
        SR[h * BM + r0]     = out0;
        SR[h * BM + r0 + 8] = out1;
    }
    __syncthreads();
    if (tid < BM)
        out[blockIdx.x * BM + tid] = SR[tid] + SR[BM + tid];
}

// ---------------------------------------------------------------------------
// Launch
// ---------------------------------------------------------------------------
extern "C" void kernel_launch(void* const* d_in, const int* in_sizes, int n_in,
                              void* d_out, int out_size) {
    const float* X = (const float*)d_in[0];   // x flat (xr[k][c] = X[k*NPTS+c])
    const float* M = (const float*)d_in[1];   // M_inv 286x286
    float* out = (float*)d_out;

    k_prep<<<NPTS / 256, 256>>>(M);

    cudaFuncSetAttribute(k_main, cudaFuncAttributeMaxDynamicSharedMemorySize,
                         SMEM_TOTAL);
    k_main<<<NPTS / BM, THREADS, SMEM_TOTAL>>>(X, out);
}

// round 15
// speedup vs baseline: 2.6065x; 1.0295x over previous
#include <cuda_runtime.h>
#include <cuda_fp16.h>
#include <cstdint>

#define NPTS 262144         // 2^18 points
#define CSH  18             // log2(NPTS)
#define CMSK 0x3FFFFu
#define DIMS 10
#define DD   286            // comb(13,3)
#define KT   288            // K padded: 18 ksteps of 16
#define ROWE 296            // A/B row stride in fp16 elems (592 B)
#define ROWB 592            // row stride bytes
#define NB   32             // N columns per streamed B chunk
#define NCH  9              // 288 / 32 chunks
#define CHB  (NB * ROWB)    // bytes per chunk (single fp16 image) = 18944
#define BM   64             // points per block (2 CTAs/SM)
#define THREADS 256
#define ONEI 10             // sentinel index -> ones row

typedef unsigned long long ull;

// B image of symmetrized upper-tri S (S[k][n] = k<n: M[k][n]+M[n][k];
// k==n: M[n][n]; else 0), single fp16, layout [chunk 9][32 rows x 592 B].
__device__ uint4 g_B[NCH * CHB / 16];
__device__ float g_ones[NPTS];
// Monomial index table, reference _exponent_nk order: i0 | i1<<8 | i2<<16.
__device__ uint32_t g_tab[DD];

// ---------------------------------------------------------------------------
// k_prep: B image + ones row + monomial table.
// ---------------------------------------------------------------------------
__global__ void k_prep(const float* __restrict__ M) {
    int idx = blockIdx.x * blockDim.x + threadIdx.x;
    if (idx < NPTS) g_ones[idx] = 1.0f;
    if (idx < KT * KT) {
        int n = idx / KT, k = idx - n * KT;
        float v = 0.0f;
        if (n < DD && k < DD) {
            if (k < n)       v = M[k * DD + n] + M[n * DD + k];
            else if (k == n) v = M[n * DD + n];
        }
        __half* B = reinterpret_cast<__half*>(g_B);
        size_t cb = (size_t)(n >> 5) * (CHB / 2);
        B[cb + (size_t)(n & 31) * ROWE + k] = __float2half_rn(v);
    }
    if (idx == 0) {
        int r = 0;
        g_tab[r++] = ONEI | (ONEI << 8) | (ONEI << 16);
        for (int j = 0; j < DIMS; j++)
            g_tab[r++] = j | (ONEI << 8) | (ONEI << 16);
        for (int j = 0; j < DIMS; j++)
            for (int a = j; a < DIMS; a++)
                g_tab[r++] = j | (a << 8) | (ONEI << 16);
        for (int j = 0; j < DIMS; j++)
            for (int a = j; a < DIMS; a++)
                for (int b = a; b < DIMS; b++)
                    g_tab[r++] = j | (a << 8) | (b << 16);
    }
}

// ---------------------------------------------------------------------------
// Base-ISA PTX helpers.
// ---------------------------------------------------------------------------
__device__ __forceinline__ void ldsm4(uint32_t r[4], uint32_t addr) {
    asm volatile(
        "ldmatrix.sync.aligned.m8n8.x4.shared.b16 {%0,%1,%2,%3}, [%4];"
        : "=r"(r[0]), "=r"(r[1]), "=r"(r[2]), "=r"(r[3]) : "r"(addr));
}
__device__ __forceinline__ void mma_f16(float c[4], const uint32_t a[4],
                                        uint32_t b0, uint32_t b1) {
    asm volatile(
        "mma.sync.aligned.m16n8k16.row.col.f32.f16.f16.f32 "
        "{%0,%1,%2,%3}, {%4,%5,%6,%7}, {%8,%9}, {%0,%1,%2,%3};"
        : "+f"(c[0]), "+f"(c[1]), "+f"(c[2]), "+f"(c[3])
        : "r"(a[0]), "r"(a[1]), "r"(a[2]), "r"(a[3]), "r"(b0), "r"(b1));
}
__device__ __forceinline__ void bulk_g2s(uint32_t dst, const void* src,
                                         uint32_t bytes, uint32_t mbar) {
    asm volatile(
        "cp.async.bulk.shared::cta.global.mbarrier::complete_tx::bytes "
        "[%0], [%1], %2, [%3];"
        :: "r"(dst), "l"(src), "r"(bytes), "r"(mbar) : "memory");
}
__device__ __forceinline__ void mbar_init(uint32_t mbar, uint32_t cnt) {
    asm volatile("mbarrier.init.shared.b64 [%0], %1;" :: "r"(mbar), "r"(cnt)
                 : "memory");
}
__device__ __forceinline__ void mbar_expect(uint32_t mbar, uint32_t bytes) {
    asm volatile("mbarrier.arrive.expect_tx.shared.b64 _, [%0], %1;"
                 :: "r"(mbar), "r"(bytes) : "memory");
}
__device__ __forceinline__ void mbar_arrive(uint32_t mbar) {
    asm volatile("mbarrier.arrive.shared.b64 _, [%0];" :: "r"(mbar)
                 : "memory");
}
__device__ __forceinline__ void mbar_wait(uint32_t mbar, uint32_t parity) {
    asm volatile(
        "{\n\t.reg .pred P1;\n\t"
        "W_%=:\n\t"
        "mbarrier.try_wait.parity.acquire.cta.shared::cta.b64 P1, [%0], %1, 0x989680;\n\t"
        "@P1 bra.uni D_%=;\n\t"
        "bra.uni W_%=;\n\t"
        "D_%=:\n\t}"
        :: "r"(mbar), "r"(parity) : "memory");
}
__device__ __forceinline__ const float* mono_ptr(const float* X, uint32_t i) {
    return (i < DIMS) ? (X + (size_t)i * NPTS) : g_ones;
}
__device__ __forceinline__ float2 up2(uint32_t u) {   // 2 packed fp16 -> f32
    __half2 h = *reinterpret_cast<__half2*>(&u);
    return __half22float2(h);
}

// SMEM map (per CTA; 2 CTAs/SM)
constexpr int SM_FULL0 = 0, SM_EMPTY0 = 16;
constexpr int SM_SR = 32;                      // [4][BM] partial sums (1 KB)
constexpr int SM_AH = 1056;
constexpr int SM_AL = SM_AH + BM * ROWB;       // 38944 (epilogue-only q_lo)
constexpr int SM_B  = SM_AL + BM * ROWB;       // 76832 (16B aligned)
constexpr int SMEM_TOTAL = SM_B + 2 * CHB;     // 114720 (112.0 KB)

// ---------------------------------------------------------------------------
// k_main: BM=64, 8 warps, 2 CTAs/SM. Warp = (wr: 32 rows, h: 16 cols,
// kq: kstep parity). Per kstep: 3 ldsm feeding 4 independent MMAs.
// K-parity split is an exact fp32 regrouping; partials summed via SR.
// ---------------------------------------------------------------------------
__global__ __launch_bounds__(THREADS, 2) void k_main(
        const float* __restrict__ X, float* __restrict__ out) {
    extern __shared__ char sm[];
    const uint32_t smb = (uint32_t)__cvta_generic_to_shared(sm);
    const int tid = threadIdx.x, w = tid >> 5, lane = tid & 31;
    const int wr = w >> 2;         // row group 0..1 (rows 32*wr..32*wr+31)
    const int h  = (w >> 1) & 1;   // N half 0/1 (chunk cols 16h..16h+15)
    const int kq = w & 1;          // kstep parity

    if (tid == 0) {
        mbar_init(smb + SM_FULL0, 1);
        mbar_init(smb + SM_FULL0 + 8, 1);
        mbar_init(smb + SM_EMPTY0, THREADS);
        mbar_init(smb + SM_EMPTY0 + 8, THREADS);
    }
    __syncthreads();
    if (tid == 0) {    // kick chunk 0 copy; overlaps A build
        mbar_expect(smb + SM_FULL0, CHB);
        bulk_g2s(smb + SM_B, g_B, CHB, smb + SM_FULL0);
    }

    // ---- A build: warp w builds 8 rows directly from L2-resident x ----
#pragma unroll
    for (int rr = 0; rr < 8; rr++) {
        const int row = w * 8 + rr;
        const int n = blockIdx.x * BM + row;
        const uint32_t flat0 = (uint32_t)n * (uint32_t)DD;
        char* ah = sm + SM_AH + row * ROWB;
        char* al = sm + SM_AL + row * ROWB;
        const uint32_t c0 = flat0 & CMSK;      // even (286 even)
        if (c0 + DD <= NPTS) {   // fast path: one monomial, contiguous window
            const uint32_t t = __ldg(g_tab + (flat0 >> CSH));
            const float* p0 = mono_ptr(X, t & 0xffu) + c0;
            const float* p1 = mono_ptr(X, (t >> 8) & 0xffu) + c0;
            const float* p2 = mono_ptr(X, (t >> 16) & 0xffu) + c0;
            for (int ip = lane; ip < 143; ip += 32) {   // 143 f32 pairs
                float2 a0 = *reinterpret_cast<const float2*>(p0 + 2 * ip);
                float2 a1 = *reinterpret_cast<const float2*>(p1 + 2 * ip);
                float2 a2 = *reinterpret_cast<const float2*>(p2 + 2 * ip);
                float v0 = (a0.x * a1.x) * a2.x;
                float v1 = (a0.y * a1.y) * a2.y;
                __half h0 = __float2half_rn(v0);
                __half h1 = __float2half_rn(v1);
                __half l0 = __float2half_rn(v0 - __half2float(h0));
                __half l1 = __float2half_rn(v1 - __half2float(h1));
                *reinterpret_cast<__half2*>(ah + ip * 4) = __halves2half2(h0, h1);
                *reinterpret_cast<__half2*>(al + ip * 4) = __halves2half2(l0, l1);
            }
        } else {                 // rare straddle: per-element
            for (int i = lane; i < DD; i += 32) {
                const uint32_t f = flat0 + i;
                const uint32_t t = __ldg(g_tab + (f >> CSH));
                const uint32_t c = f & CMSK;
                float v = (__ldg(mono_ptr(X, t & 0xffu) + c) *
                           __ldg(mono_ptr(X, (t >> 8) & 0xffu) + c)) *
                          __ldg(mono_ptr(X, (t >> 16) & 0xffu) + c);
                __half vh = __float2half_rn(v);
                __half vl = __float2half_rn(v - __half2float(vh));
                *reinterpret_cast<__half*>(ah + i * 2) = vh;
                *reinterpret_cast<__half*>(al + i * 2) = vl;
            }
        }
        if (lane < 2) {          // zero pad i = 286, 287
            *reinterpret_cast<uint32_t*>(ah + 572) = 0u;
            *reinterpret_cast<uint32_t*>(al + 572) = 0u;
        }
    }
    __syncthreads();

    // ldmatrix addressing: A row groups 32*wr..+15 and +16..+31.
    const uint32_t aRow0 = smb + SM_AH + (wr * 32 + (lane & 15)) * ROWB +
                           (lane >> 4) * 16;
    const uint32_t aRow1 = aRow0 + 16 * ROWB;
    const uint32_t bOff = (h * 16 + ((lane >> 4) & 1) * 8 + (lane & 7)) * ROWB +
                          ((lane >> 3) & 1) * 16;

    float o00 = 0.f, o01 = 0.f, o10 = 0.f, o11 = 0.f;   // rows r0,+8,+16,+24
    const int r0 = wr * 32 + (lane >> 2);
    const uint32_t qh0 = smb + SM_AH + r0 * ROWB + (lane & 3) * 4;
    const uint32_t ql0 = smb + SM_AL + r0 * ROWB + (lane & 3) * 4;

    for (int c = 0; c < NCH; c++) {
        const int b = c & 1;
        if (tid == 0 && c + 1 < NCH) {
            const int b2 = (c + 1) & 1;
            if (c >= 1)
                mbar_wait(smb + SM_EMPTY0 + 8 * b2, ((c - 1) >> 1) & 1);
            mbar_expect(smb + SM_FULL0 + 8 * b2, CHB);
            bulk_g2s(smb + SM_B + b2 * CHB,
                     reinterpret_cast<const char*>(g_B) + (size_t)(c + 1) * CHB,
                     CHB, smb + SM_FULL0 + 8 * b2);
        }
        mbar_wait(smb + SM_FULL0 + 8 * b, (c >> 1) & 1);

        const uint32_t bm = smb + SM_B + b * CHB + bOff;

        // 4 independent accumulators: C[rowgroup(2)][n8(2)]
        float C[2][2][4];
#pragma unroll
        for (int g = 0; g < 2; g++)
#pragma unroll
            for (int q = 0; q < 2; q++)
#pragma unroll
                for (int u = 0; u < 4; u++) C[g][q][u] = 0.f;

        const int kmax = 2 * c + 2;    // even; each kq gets c+1 ksteps

        uint32_t fa0[2][4], fa1[2][4], fm[2][4];
        {
            const uint32_t ko = kq * 32;
            ldsm4(fa0[0], aRow0 + ko);
            ldsm4(fa1[0], aRow1 + ko);
            ldsm4(fm[0], bm + ko);
        }
        int cur = 0;
#pragma unroll 2
        for (int k = kq; k < kmax; k += 2) {
            const int nxt = cur ^ 1;
            if (k + 2 < kmax) {
                const uint32_t ko = (k + 2) * 32;
                ldsm4(fa0[nxt], aRow0 + ko);
                ldsm4(fa1[nxt], aRow1 + ko);
                ldsm4(fm[nxt], bm + ko);
            }
            mma_f16(C[0][0], fa0[cur], fm[cur][0], fm[cur][1]);
            mma_f16(C[0][1], fa0[cur], fm[cur][2], fm[cur][3]);
            mma_f16(C[1][0], fa1[cur], fm[cur][0], fm[cur][1]);
            mma_f16(C[1][1], fa1[cur], fm[cur][2], fm[cur][3]);
            cur = nxt;
        }
        mbar_arrive(smb + SM_EMPTY0 + 8 * b);

        // ---- Fused epilogue: out += C ∘ q (exact q = qh + ql), 16 cols,
        //      rows r0, r0+8 (group 0) and r0+16, r0+24 (group 1).
        const int jb = c * 32 + h * 16;
#pragma unroll
        for (int nc = 0; nc < 2; nc++) {
            const uint32_t jo = (jb + nc * 8) * 2;
#pragma unroll
            for (int g = 0; g < 2; g++) {
                const uint32_t ro = g * 16 * ROWB;
                uint32_t vh, vl, wh, wl;
                asm volatile("ld.shared.b32 %0, [%1];" : "=r"(vh)
                             : "r"(qh0 + ro + jo));
                asm volatile("ld.shared.b32 %0, [%1];" : "=r"(vl)
                             : "r"(ql0 + ro + jo));
                asm volatile("ld.shared.b32 %0, [%1];" : "=r"(wh)
                             : "r"(qh0 + ro + 8 * ROWB + jo));
                asm volatile("ld.shared.b32 %0, [%1];" : "=r"(wl)
                             : "r"(ql0 + ro + 8 * ROWB + jo));
                float2 vhf = up2(vh), vlf = up2(vl);
                float2 whf = up2(wh), wlf = up2(wl);
                float qe = vhf.x + vlf.x, qo = vhf.y + vlf.y;
                float re = whf.x + wlf.x, ro2 = whf.y + wlf.y;
                if (g == 0) {
                    o00 = fmaf(C[0][nc][0], qe, o00);
                    o00 = fmaf(C[0][nc][1], qo, o00);
                    o01 = fmaf(C[0][nc][2], re, o01);
                    o01 = fmaf(C[0][nc][3], ro2, o01);
                } else {
                    o10 = fmaf(C[1][nc][0], qe, o10);
                    o10 = fmaf(C[1][nc][1], qo, o10);
                    o11 = fmaf(C[1][nc][2], re, o11);
                    o11 = fmaf(C[1][nc][3], ro2, o11);
                }
            }
        }
    }

    // Reduce the 4 j-phases within lane quads.
    o00 += __shfl_xor_sync(0xffffffffu, o00, 1);
    o00 += __shfl_xor_sync(0xffffffffu, o00, 2);
    o01 += __shfl_xor_sync(0xffffffffu, o01, 1);
    o01 += __shfl_xor_sync(0xffffffffu, o01, 2);
    o10 += __shfl_xor_sync(0xffffffffu, o10, 1);
    o10 += __shfl_xor_sync(0xffffffffu, o10, 2);
    o11 += __shfl_xor_sync(0xffffffffu, o11, 1);
    o11 += __shfl_xor_sync(0xffffffffu, o11, 2);

    // Combine 4 partials per point (2 h x 2 kq) via smem.
    float* SR = reinterpret_cast<float*>(sm + SM_SR);
    const int p = (h << 1) | kq;
    if ((lane & 3) == 0) {
        SR[p * BM + r0]      = o00;
        SR[p * BM + r0 + 8]  = o01;
        SR[p * BM + r0 + 16] = o10;
        SR[p * BM + r0 + 24] = o11;
    }
    __syncthreads();
    if (tid < BM)
        out[blockIdx.x * BM + tid] =
            (SR[tid] + SR[BM + tid]) + (SR[2 * BM + tid] + SR[3 * BM + tid]);
}

// ---------------------------------------------------------------------------
// Launch
// ---------------------------------------------------------------------------
extern "C" void kernel_launch(void* const* d_in, const int* in_sizes, int n_in,
                              void* d_out, int out_size) {
    const float* X = (const float*)d_in[0];   // x flat (xr[k][c] = X[k*NPTS+c])
    const float* M = (const float*)d_in[1];   // M_inv 286x286
    float* out = (float*)d_out;

    k_prep<<<NPTS / 256, 256>>>(M);

    cudaFuncSetAttribute(k_main, cudaFuncAttributeMaxDynamicSharedMemorySize,
                         SMEM_TOTAL);
    k_main<<<NPTS / BM, THREADS, SMEM_TOTAL>>>(X, out);
}

// round 16
// speedup vs baseline: 2.9085x; 1.1159x over previous
#include <cuda_runtime.h>
#include <cuda_fp16.h>
#include <cstdint>

#define NPTS 262144         // 2^18 points
#define CSH  18             // log2(NPTS)
#define CMSK 0x3FFFFu
#define DIMS 10
#define DD   286            // comb(13,3)
#define KT   288            // K padded: 18 ksteps of 16
#define ROWE 296            // A/B row stride in fp16 elems (592 B)
#define ROWB 592            // row stride bytes
#define NB   32             // N columns per streamed B chunk
#define NCH  9              // 288 / 32 chunks
#define CHB  (NB * ROWB)    // bytes per chunk (single fp16 image) = 18944
#define BM   64             // points per block
#define THREADS 256
#define ONEI 10             // sentinel index -> ones row

typedef unsigned long long ull;

// B image of symmetrized upper-tri S (S[k][n] = k<n: M[k][n]+M[n][k];
// k==n: M[n][n]; else 0), single fp16, layout [chunk 9][32 rows x 592 B].
__device__ uint4 g_B[NCH * CHB / 16];
__device__ float g_ones[NPTS];
// Monomial index table, reference _exponent_nk order: i0 | i1<<8 | i2<<16.
__device__ uint32_t g_tab[DD];

// ---------------------------------------------------------------------------
// k_prep: B image + ones row + monomial table.
// ---------------------------------------------------------------------------
__global__ void k_prep(const float* __restrict__ M) {
    int idx = blockIdx.x * blockDim.x + threadIdx.x;
    if (idx < NPTS) g_ones[idx] = 1.0f;
    if (idx < KT * KT) {
        int n = idx / KT, k = idx - n * KT;
        float v = 0.0f;
        if (n < DD && k < DD) {
            if (k < n)       v = M[k * DD + n] + M[n * DD + k];
            else if (k == n) v = M[n * DD + n];
        }
        __half* B = reinterpret_cast<__half*>(g_B);
        size_t cb = (size_t)(n >> 5) * (CHB / 2);
        B[cb + (size_t)(n & 31) * ROWE + k] = __float2half_rn(v);
    }
    if (idx == 0) {
        int r = 0;
        g_tab[r++] = ONEI | (ONEI << 8) | (ONEI << 16);
        for (int j = 0; j < DIMS; j++)
            g_tab[r++] = j | (ONEI << 8) | (ONEI << 16);
        for (int j = 0; j < DIMS; j++)
            for (int a = j; a < DIMS; a++)
                g_tab[r++] = j | (a << 8) | (ONEI << 16);
        for (int j = 0; j < DIMS; j++)
            for (int a = j; a < DIMS; a++)
                for (int b = a; b < DIMS; b++)
                    g_tab[r++] = j | (a << 8) | (b << 16);
    }
}

// ---------------------------------------------------------------------------
// Base-ISA PTX helpers.
// ---------------------------------------------------------------------------
__device__ __forceinline__ void ldsm4(uint32_t r[4], uint32_t addr) {
    asm volatile(
        "ldmatrix.sync.aligned.m8n8.x4.shared.b16 {%0,%1,%2,%3}, [%4];"
        : "=r"(r[0]), "=r"(r[1]), "=r"(r[2]), "=r"(r[3]) : "r"(addr));
}
__device__ __forceinline__ void mma_f16(float c[4], const uint32_t a[4],
                                        uint32_t b0, uint32_t b1) {
    asm volatile(
        "mma.sync.aligned.m16n8k16.row.col.f32.f16.f16.f32 "
        "{%0,%1,%2,%3}, {%4,%5,%6,%7}, {%8,%9}, {%0,%1,%2,%3};"
        : "+f"(c[0]), "+f"(c[1]), "+f"(c[2]), "+f"(c[3])
        : "r"(a[0]), "r"(a[1]), "r"(a[2]), "r"(a[3]), "r"(b0), "r"(b1));
}
__device__ __forceinline__ void bulk_g2s(uint32_t dst, const void* src,
                                         uint32_t bytes, uint32_t mbar) {
    asm volatile(
        "cp.async.bulk.shared::cta.global.mbarrier::complete_tx::bytes "
        "[%0], [%1], %2, [%3];"
        :: "r"(dst), "l"(src), "r"(bytes), "r"(mbar) : "memory");
}
__device__ __forceinline__ void mbar_init(uint32_t mbar, uint32_t cnt) {
    asm volatile("mbarrier.init.shared.b64 [%0], %1;" :: "r"(mbar), "r"(cnt)
                 : "memory");
}
__device__ __forceinline__ void mbar_expect(uint32_t mbar, uint32_t bytes) {
    asm volatile("mbarrier.arrive.expect_tx.shared.b64 _, [%0], %1;"
                 :: "r"(mbar), "r"(bytes) : "memory");
}
__device__ __forceinline__ void mbar_arrive(uint32_t mbar) {
    asm volatile("mbarrier.arrive.shared.b64 _, [%0];" :: "r"(mbar)
                 : "memory");
}
__device__ __forceinline__ void mbar_wait(uint32_t mbar, uint32_t parity) {
    asm volatile(
        "{\n\t.reg .pred P1;\n\t"
        "W_%=:\n\t"
        "mbarrier.try_wait.parity.acquire.cta.shared::cta.b64 P1, [%0], %1, 0x989680;\n\t"
        "@P1 bra.uni D_%=;\n\t"
        "bra.uni W_%=;\n\t"
        "D_%=:\n\t}"
        :: "r"(mbar), "r"(parity) : "memory");
}
__device__ __forceinline__ const float* mono_ptr(const float* X, uint32_t i) {
    return (i < DIMS) ? (X + (size_t)i * NPTS) : g_ones;
}
__device__ __forceinline__ float2 up2(uint32_t u) {   // 2 packed fp16 -> f32
    __half2 h = *reinterpret_cast<__half2*>(&u);
    return __half22float2(h);
}

// SMEM map (per CTA; 3 CTAs/SM: 3 x 76832 B = 230.5 KB <= 233 KB)
constexpr int SM_FULL0 = 0, SM_EMPTY0 = 16;
constexpr int SM_SR = 32;                      // [4][BM] partial sums (1 KB)
constexpr int SM_AH = 1056;
constexpr int SM_B  = SM_AH + BM * ROWB;       // 38944 (16B aligned)
constexpr int SMEM_TOTAL = SM_B + 2 * CHB;     // 76832 (75.0 KB)

// ---------------------------------------------------------------------------
// k_main: BM=64, 8 warps, 3 CTAs/SM. Warp = (wr: 32 rows, h: 16 cols,
// kq: kstep parity). A = fp16(q) only (lo-half dropped; error budget holds).
// Epilogue reads q via ldmatrix fragments that map 1:1 onto the C layout.
// ---------------------------------------------------------------------------
__global__ __launch_bounds__(THREADS, 3) void k_main(
        const float* __restrict__ X, float* __restrict__ out) {
    extern __shared__ char sm[];
    const uint32_t smb = (uint32_t)__cvta_generic_to_shared(sm);
    const int tid = threadIdx.x, w = tid >> 5, lane = tid & 31;
    const int wr = w >> 2;         // row group 0..1 (rows 32*wr..32*wr+31)
    const int h  = (w >> 1) & 1;   // N half 0/1 (chunk cols 16h..16h+15)
    const int kq = w & 1;          // kstep parity

    if (tid == 0) {
        mbar_init(smb + SM_FULL0, 1);
        mbar_init(smb + SM_FULL0 + 8, 1);
        mbar_init(smb + SM_EMPTY0, THREADS);
        mbar_init(smb + SM_EMPTY0 + 8, THREADS);
    }
    __syncthreads();
    if (tid == 0) {    // kick chunk 0 copy; overlaps A build
        mbar_expect(smb + SM_FULL0, CHB);
        bulk_g2s(smb + SM_B, g_B, CHB, smb + SM_FULL0);
    }

    // ---- A build: warp w builds 8 rows (fp16 hi only) from L2-resident x ----
#pragma unroll
    for (int rr = 0; rr < 8; rr++) {
        const int row = w * 8 + rr;
        const int n = blockIdx.x * BM + row;
        const uint32_t flat0 = (uint32_t)n * (uint32_t)DD;
        char* ah = sm + SM_AH + row * ROWB;
        const uint32_t c0 = flat0 & CMSK;      // even (286 even)
        if (c0 + DD <= NPTS) {   // fast path: one monomial, contiguous window
            const uint32_t t = __ldg(g_tab + (flat0 >> CSH));
            const float* p0 = mono_ptr(X, t & 0xffu) + c0;
            const float* p1 = mono_ptr(X, (t >> 8) & 0xffu) + c0;
            const float* p2 = mono_ptr(X, (t >> 16) & 0xffu) + c0;
            for (int ip = lane; ip < 143; ip += 32) {   // 143 f32 pairs
                float2 a0 = *reinterpret_cast<const float2*>(p0 + 2 * ip);
                float2 a1 = *reinterpret_cast<const float2*>(p1 + 2 * ip);
                float2 a2 = *reinterpret_cast<const float2*>(p2 + 2 * ip);
                float v0 = (a0.x * a1.x) * a2.x;
                float v1 = (a0.y * a1.y) * a2.y;
                *reinterpret_cast<__half2*>(ah + ip * 4) =
                    __halves2half2(__float2half_rn(v0), __float2half_rn(v1));
            }
        } else {                 // rare straddle: per-element
            for (int i = lane; i < DD; i += 32) {
                const uint32_t f = flat0 + i;
                const uint32_t t = __ldg(g_tab + (f >> CSH));
                const uint32_t c = f & CMSK;
                float v = (__ldg(mono_ptr(X, t & 0xffu) + c) *
                           __ldg(mono_ptr(X, (t >> 8) & 0xffu) + c)) *
                          __ldg(mono_ptr(X, (t >> 16) & 0xffu) + c);
                *reinterpret_cast<__half*>(ah + i * 2) = __float2half_rn(v);
            }
        }
        if (lane == 0)           // zero pad i = 286, 287
            *reinterpret_cast<uint32_t*>(ah + 572) = 0u;
    }
    __syncthreads();

    // ldmatrix addressing: A row groups 32*wr..+15 and +16..+31.
    const uint32_t aRow0 = smb + SM_AH + (wr * 32 + (lane & 15)) * ROWB +
                           (lane >> 4) * 16;
    const uint32_t aRow1 = aRow0 + 16 * ROWB;
    const uint32_t bOff = (h * 16 + ((lane >> 4) & 1) * 8 + (lane & 7)) * ROWB +
                          ((lane >> 3) & 1) * 16;
    // Epilogue q-tile bases (same fragment geometry as A, per row group).
    const uint32_t qt0 = aRow0;    // rows wr*32..+15
    const uint32_t qt1 = aRow1;    // rows wr*32+16..+31

    float o00 = 0.f, o01 = 0.f, o10 = 0.f, o11 = 0.f;   // rows r0,+8,+16,+24
    const int r0 = wr * 32 + (lane >> 2);

    for (int c = 0; c < NCH; c++) {
        const int b = c & 1;
        if (tid == 0 && c + 1 < NCH) {
            const int b2 = (c + 1) & 1;
            if (c >= 1)
                mbar_wait(smb + SM_EMPTY0 + 8 * b2, ((c - 1) >> 1) & 1);
            mbar_expect(smb + SM_FULL0 + 8 * b2, CHB);
            bulk_g2s(smb + SM_B + b2 * CHB,
                     reinterpret_cast<const char*>(g_B) + (size_t)(c + 1) * CHB,
                     CHB, smb + SM_FULL0 + 8 * b2);
        }
        mbar_wait(smb + SM_FULL0 + 8 * b, (c >> 1) & 1);

        const uint32_t bm = smb + SM_B + b * CHB + bOff;

        // 4 independent accumulators: C[rowgroup(2)][n8(2)]
        float C[2][2][4];
#pragma unroll
        for (int g = 0; g < 2; g++)
#pragma unroll
            for (int q = 0; q < 2; q++)
#pragma unroll
                for (int u = 0; u < 4; u++) C[g][q][u] = 0.f;

        const int kmax = 2 * c + 2;    // even; each kq gets c+1 ksteps

        uint32_t fa0[2][4], fa1[2][4], fm[2][4];
        {
            const uint32_t ko = kq * 32;
            ldsm4(fa0[0], aRow0 + ko);
            ldsm4(fa1[0], aRow1 + ko);
            ldsm4(fm[0], bm + ko);
        }
        int cur = 0;
#pragma unroll 2
        for (int k = kq; k < kmax; k += 2) {
            const int nxt = cur ^ 1;
            if (k + 2 < kmax) {
                const uint32_t ko = (k + 2) * 32;
                ldsm4(fa0[nxt], aRow0 + ko);
                ldsm4(fa1[nxt], aRow1 + ko);
                ldsm4(fm[nxt], bm + ko);
            }
            mma_f16(C[0][0], fa0[cur], fm[cur][0], fm[cur][1]);
            mma_f16(C[0][1], fa0[cur], fm[cur][2], fm[cur][3]);
            mma_f16(C[1][0], fa1[cur], fm[cur][0], fm[cur][1]);
            mma_f16(C[1][1], fa1[cur], fm[cur][2], fm[cur][3]);
            cur = nxt;
        }
        mbar_arrive(smb + SM_EMPTY0 + 8 * b);

        // ---- Fused epilogue via ldmatrix: q fragments map 1:1 onto C ----
        //   a0: rows g+0..7 cols jb..jb+7   -> C[g][0][0,1]
        //   a1: rows g+8..15 cols jb..jb+7  -> C[g][0][2,3]
        //   a2: rows g+0..7 cols jb+8..15   -> C[g][1][0,1]
        //   a3: rows g+8..15 cols jb+8..15  -> C[g][1][2,3]
        const uint32_t jo = (uint32_t)(c * 32 + h * 16) * 2;
        uint32_t q0[4], q1[4];
        ldsm4(q0, qt0 + jo);
        ldsm4(q1, qt1 + jo);
        float2 f;
        f = up2(q0[0]); o00 = fmaf(C[0][0][0], f.x, fmaf(C[0][0][1], f.y, o00));
        f = up2(q0[1]); o01 = fmaf(C[0][0][2], f.x, fmaf(C[0][0][3], f.y, o01));
        f = up2(q0[2]); o00 = fmaf(C[0][1][0], f.x, fmaf(C[0][1][1], f.y, o00));
        f = up2(q0[3]); o01 = fmaf(C[0][1][2], f.x, fmaf(C[0][1][3], f.y, o01));
        f = up2(q1[0]); o10 = fmaf(C[1][0][0], f.x, fmaf(C[1][0][1], f.y, o10));
        f = up2(q1[1]); o11 = fmaf(C[1][0][2], f.x, fmaf(C[1][0][3], f.y, o11));
        f = up2(q1[2]); o10 = fmaf(C[1][1][0], f.x, fmaf(C[1][1][1], f.y, o10));
        f = up2(q1[3]); o11 = fmaf(C[1][1][2], f.x, fmaf(C[1][1][3], f.y, o11));
    }

    // Reduce the 4 j-phases within lane quads.
    o00 += __shfl_xor_sync(0xffffffffu, o00, 1);
    o00 += __shfl_xor_sync(0xffffffffu, o00, 2);
    o01 += __shfl_xor_sync(0xffffffffu, o01, 1);
    o01 += __shfl_xor_sync(0xffffffffu, o01, 2);
    o10 += __shfl_xor_sync(0xffffffffu, o10, 1);
    o10 += __shfl_xor_sync(0xffffffffu, o10, 2);
    o11 += __shfl_xor_sync(0xffffffffu, o11, 1);
    o11 += __shfl_xor_sync(0xffffffffu, o11, 2);

    // Combine 4 partials per point (2 h x 2 kq) via smem.
    float* SR = reinterpret_cast<float*>(sm + SM_SR);
    const int p = (h << 1) | kq;
    if ((lane & 3) == 0) {
        SR[p * BM + r0]      = o00;
        SR[p * BM + r0 + 8]  = o01;
        SR[p * BM + r0 + 16] = o10;
        SR[p * BM + r0 + 24] = o11;
    }
    __syncthreads();
    if (tid < BM)
        out[blockIdx.x * BM + tid] =
            (SR[tid] + SR[BM + tid]) + (SR[2 * BM + tid] + SR[3 * BM + tid]);
}

// ---------------------------------------------------------------------------
// Launch
// ---------------------------------------------------------------------------
extern "C" void kernel_launch(void* const* d_in, const int* in_sizes, int n_in,
                              void* d_out, int out_size) {
    const float* X = (const float*)d_in[0];   // x flat (xr[k][c] = X[k*NPTS+c])
    const float* M = (const float*)d_in[1];   // M_inv 286x286
    float* out = (float*)d_out;

    k_prep<<<NPTS / 256, 256>>>(M);

    cudaFuncSetAttribute(k_main, cudaFuncAttributeMaxDynamicSharedMemorySize,
                         SMEM_TOTAL);
    k_main<<<NPTS / BM, THREADS, SMEM_TOTAL>>>(X, out);
}

// round 17
// speedup vs baseline: 3.7097x; 1.2755x over previous
#include <cuda_runtime.h>
#include <cuda_fp16.h>
#include <cstdint>

#define NPTS 262144         // 2^18 points
#define CSH  18             // log2(NPTS)
#define CMSK 0x3FFFFu
#define DIMS 10
#define DD   286            // comb(13,3)
#define KT   288            // K padded: 18 ksteps of 16
#define ROWE 296            // A/B row stride in fp16 elems (592 B)
#define ROWB 592            // row stride bytes
#define NB   32             // N columns per streamed B chunk
#define NCH  9              // 288 / 32 chunks
#define CHB  (NB * ROWB)    // bytes per chunk (single fp16 image) = 18944
#define BM   64             // points per block
#define THREADS 256
#define ONEI 10             // sentinel index -> ones row

typedef unsigned long long ull;

// B image of symmetrized upper-tri S (S[k][n] = k<n: M[k][n]+M[n][k];
// k==n: M[n][n]; else 0), single fp16, layout [chunk 9][32 rows x 592 B].
__device__ uint4 g_B[NCH * CHB / 16];
__device__ float g_ones[NPTS];
// Monomial index table, reference _exponent_nk order: i0 | i1<<8 | i2<<16.
__device__ uint32_t g_tab[DD];

// ---------------------------------------------------------------------------
// k_prep: B image + ones row + monomial table.
// ---------------------------------------------------------------------------
__global__ void k_prep(const float* __restrict__ M) {
    int idx = blockIdx.x * blockDim.x + threadIdx.x;
    if (idx < NPTS) g_ones[idx] = 1.0f;
    if (idx < KT * KT) {
        int n = idx / KT, k = idx - n * KT;
        float v = 0.0f;
        if (n < DD && k < DD) {
            if (k < n)       v = M[k * DD + n] + M[n * DD + k];
            else if (k == n) v = M[n * DD + n];
        }
        __half* B = reinterpret_cast<__half*>(g_B);
        size_t cb = (size_t)(n >> 5) * (CHB / 2);
        B[cb + (size_t)(n & 31) * ROWE + k] = __float2half_rn(v);
    }
    if (idx == 0) {
        int r = 0;
        g_tab[r++] = ONEI | (ONEI << 8) | (ONEI << 16);
        for (int j = 0; j < DIMS; j++)
            g_tab[r++] = j | (ONEI << 8) | (ONEI << 16);
        for (int j = 0; j < DIMS; j++)
            for (int a = j; a < DIMS; a++)
                g_tab[r++] = j | (a << 8) | (ONEI << 16);
        for (int j = 0; j < DIMS; j++)
            for (int a = j; a < DIMS; a++)
                for (int b = a; b < DIMS; b++)
                    g_tab[r++] = j | (a << 8) | (b << 16);
    }
}

// ---------------------------------------------------------------------------
// Base-ISA PTX helpers.
// ---------------------------------------------------------------------------
__device__ __forceinline__ void ldsm4(uint32_t r[4], uint32_t addr) {
    asm volatile(
        "ldmatrix.sync.aligned.m8n8.x4.shared.b16 {%0,%1,%2,%3}, [%4];"
        : "=r"(r[0]), "=r"(r[1]), "=r"(r[2]), "=r"(r[3]) : "r"(addr));
}
__device__ __forceinline__ void mma_f16(float c[4], const uint32_t a[4],
                                        uint32_t b0, uint32_t b1) {
    asm volatile(
        "mma.sync.aligned.m16n8k16.row.col.f32.f16.f16.f32 "
        "{%0,%1,%2,%3}, {%4,%5,%6,%7}, {%8,%9}, {%0,%1,%2,%3};"
        : "+f"(c[0]), "+f"(c[1]), "+f"(c[2]), "+f"(c[3])
        : "r"(a[0]), "r"(a[1]), "r"(a[2]), "r"(a[3]), "r"(b0), "r"(b1));
}
__device__ __forceinline__ void bulk_g2s(uint32_t dst, const void* src,
                                         uint32_t bytes, uint32_t mbar) {
    asm volatile(
        "cp.async.bulk.shared::cta.global.mbarrier::complete_tx::bytes "
        "[%0], [%1], %2, [%3];"
        :: "r"(dst), "l"(src), "r"(bytes), "r"(mbar) : "memory");
}
__device__ __forceinline__ void mbar_init(uint32_t mbar, uint32_t cnt) {
    asm volatile("mbarrier.init.shared.b64 [%0], %1;" :: "r"(mbar), "r"(cnt)
                 : "memory");
}
__device__ __forceinline__ void mbar_expect(uint32_t mbar, uint32_t bytes) {
    asm volatile("mbarrier.arrive.expect_tx.shared.b64 _, [%0], %1;"
                 :: "r"(mbar), "r"(bytes) : "memory");
}
__device__ __forceinline__ void mbar_arrive(uint32_t mbar) {
    asm volatile("mbarrier.arrive.shared.b64 _, [%0];" :: "r"(mbar)
                 : "memory");
}
__device__ __forceinline__ void mbar_wait(uint32_t mbar, uint32_t parity) {
    asm volatile(
        "{\n\t.reg .pred P1;\n\t"
        "W_%=:\n\t"
        "mbarrier.try_wait.parity.acquire.cta.shared::cta.b64 P1, [%0], %1, 0x989680;\n\t"
        "@P1 bra.uni D_%=;\n\t"
        "bra.uni W_%=;\n\t"
        "D_%=:\n\t}"
        :: "r"(mbar), "r"(parity) : "memory");
}
__device__ __forceinline__ const float* mono_ptr(const float* X, uint32_t i) {
    return (i < DIMS) ? (X + (size_t)i * NPTS) : g_ones;
}
__device__ __forceinline__ float2 up2(uint32_t u) {   // 2 packed fp16 -> f32
    __half2 h = *reinterpret_cast<__half2*>(&u);
    return __half22float2(h);
}

// SMEM map (per CTA; 3 CTAs/SM: 3 x (75808 + 1024 reserve) = 230496 <= limit)
// SR partial-sum array is ALIASED into B buffer 0 (dead after last chunk's
// MMAs; a __syncthreads() separates last B read from first SR write).
constexpr int SM_FULL0 = 0, SM_EMPTY0 = 16;
constexpr int SM_AH = 32;                      // 16B aligned
constexpr int SM_B  = SM_AH + BM * ROWB;       // 37920 (16B aligned)
constexpr int SMEM_TOTAL = SM_B + 2 * CHB;     // 75808 (74.03 KB)

// ---------------------------------------------------------------------------
// k_main: BM=64, 8 warps, 3 CTAs/SM. Warp = (wr: 32 rows, h: 16 cols,
// kq: kstep parity). A = fp16(q); epilogue via ldmatrix fragments.
// ---------------------------------------------------------------------------
__global__ __launch_bounds__(THREADS, 3) void k_main(
        const float* __restrict__ X, float* __restrict__ out) {
    extern __shared__ char sm[];
    const uint32_t smb = (uint32_t)__cvta_generic_to_shared(sm);
    const int tid = threadIdx.x, w = tid >> 5, lane = tid & 31;
    const int wr = w >> 2;         // row group 0..1 (rows 32*wr..32*wr+31)
    const int h  = (w >> 1) & 1;   // N half 0/1 (chunk cols 16h..16h+15)
    const int kq = w & 1;          // kstep parity

    if (tid == 0) {
        mbar_init(smb + SM_FULL0, 1);
        mbar_init(smb + SM_FULL0 + 8, 1);
        mbar_init(smb + SM_EMPTY0, THREADS);
        mbar_init(smb + SM_EMPTY0 + 8, THREADS);
    }
    __syncthreads();
    if (tid == 0) {    // kick chunk 0 copy; overlaps A build
        mbar_expect(smb + SM_FULL0, CHB);
        bulk_g2s(smb + SM_B, g_B, CHB, smb + SM_FULL0);
    }

    // ---- A build: warp w builds 8 rows (fp16) from L2-resident x ----
#pragma unroll
    for (int rr = 0; rr < 8; rr++) {
        const int row = w * 8 + rr;
        const int n = blockIdx.x * BM + row;
        const uint32_t flat0 = (uint32_t)n * (uint32_t)DD;
        char* ah = sm + SM_AH + row * ROWB;
        const uint32_t c0 = flat0 & CMSK;      // even (286 even)
        if (c0 + DD <= NPTS) {   // fast path: one monomial, contiguous window
            const uint32_t t = __ldg(g_tab + (flat0 >> CSH));
            const float* p0 = mono_ptr(X, t & 0xffu) + c0;
            const float* p1 = mono_ptr(X, (t >> 8) & 0xffu) + c0;
            const float* p2 = mono_ptr(X, (t >> 16) & 0xffu) + c0;
            for (int ip = lane; ip < 143; ip += 32) {   // 143 f32 pairs
                float2 a0 = *reinterpret_cast<const float2*>(p0 + 2 * ip);
                float2 a1 = *reinterpret_cast<const float2*>(p1 + 2 * ip);
                float2 a2 = *reinterpret_cast<const float2*>(p2 + 2 * ip);
                float v0 = (a0.x * a1.x) * a2.x;
                float v1 = (a0.y * a1.y) * a2.y;
                *reinterpret_cast<__half2*>(ah + ip * 4) =
                    __halves2half2(__float2half_rn(v0), __float2half_rn(v1));
            }
        } else {                 // rare straddle: per-element
            for (int i = lane; i < DD; i += 32) {
                const uint32_t f = flat0 + i;
                const uint32_t t = __ldg(g_tab + (f >> CSH));
                const uint32_t c = f & CMSK;
                float v = (__ldg(mono_ptr(X, t & 0xffu) + c) *
                           __ldg(mono_ptr(X, (t >> 8) & 0xffu) + c)) *
                          __ldg(mono_ptr(X, (t >> 16) & 0xffu) + c);
                *reinterpret_cast<__half*>(ah + i * 2) = __float2half_rn(v);
            }
        }
        if (lane == 0)           // zero pad i = 286, 287
            *reinterpret_cast<uint32_t*>(ah + 572) = 0u;
    }
    __syncthreads();

    // ldmatrix addressing: A row groups 32*wr..+15 and +16..+31.
    const uint32_t aRow0 = smb + SM_AH + (wr * 32 + (lane & 15)) * ROWB +
                           (lane >> 4) * 16;
    const uint32_t aRow1 = aRow0 + 16 * ROWB;
    const uint32_t bOff = (h * 16 + ((lane >> 4) & 1) * 8 + (lane & 7)) * ROWB +
                          ((lane >> 3) & 1) * 16;

    float o00 = 0.f, o01 = 0.f, o10 = 0.f, o11 = 0.f;   // rows r0,+8,+16,+24
    const int r0 = wr * 32 + (lane >> 2);

    for (int c = 0; c < NCH; c++) {
        const int b = c & 1;
        if (tid == 0 && c + 1 < NCH) {
            const int b2 = (c + 1) & 1;
            if (c >= 1)
                mbar_wait(smb + SM_EMPTY0 + 8 * b2, ((c - 1) >> 1) & 1);
            mbar_expect(smb + SM_FULL0 + 8 * b2, CHB);
            bulk_g2s(smb + SM_B + b2 * CHB,
                     reinterpret_cast<const char*>(g_B) + (size_t)(c + 1) * CHB,
                     CHB, smb + SM_FULL0 + 8 * b2);
        }
        mbar_wait(smb + SM_FULL0 + 8 * b, (c >> 1) & 1);

        const uint32_t bm = smb + SM_B + b * CHB + bOff;

        // 4 independent accumulators: C[rowgroup(2)][n8(2)]
        float C[2][2][4];
#pragma unroll
        for (int g = 0; g < 2; g++)
#pragma unroll
            for (int q = 0; q < 2; q++)
#pragma unroll
                for (int u = 0; u < 4; u++) C[g][q][u] = 0.f;

        const int kmax = 2 * c + 2;    // even; each kq gets c+1 ksteps

        uint32_t fa0[2][4], fa1[2][4], fm[2][4];
        {
            const uint32_t ko = kq * 32;
            ldsm4(fa0[0], aRow0 + ko);
            ldsm4(fa1[0], aRow1 + ko);
            ldsm4(fm[0], bm + ko);
        }
        int cur = 0;
#pragma unroll 2
        for (int k = kq; k < kmax; k += 2) {
            const int nxt = cur ^ 1;
            if (k + 2 < kmax) {
                const uint32_t ko = (k + 2) * 32;
                ldsm4(fa0[nxt], aRow0 + ko);
                ldsm4(fa1[nxt], aRow1 + ko);
                ldsm4(fm[nxt], bm + ko);
            }
            mma_f16(C[0][0], fa0[cur], fm[cur][0], fm[cur][1]);
            mma_f16(C[0][1], fa0[cur], fm[cur][2], fm[cur][3]);
            mma_f16(C[1][0], fa1[cur], fm[cur][0], fm[cur][1]);
            mma_f16(C[1][1], fa1[cur], fm[cur][2], fm[cur][3]);
            cur = nxt;
        }
        mbar_arrive(smb + SM_EMPTY0 + 8 * b);

        // ---- Fused epilogue via ldmatrix: q fragments map 1:1 onto C ----
        const uint32_t jo = (uint32_t)(c * 32 + h * 16) * 2;
        uint32_t q0[4], q1[4];
        ldsm4(q0, aRow0 + jo);
        ldsm4(q1, aRow1 + jo);
        float2 f;
        f = up2(q0[0]); o00 = fmaf(C[0][0][0], f.x, fmaf(C[0][0][1], f.y, o00));
        f = up2(q0[1]); o01 = fmaf(C[0][0][2], f.x, fmaf(C[0][0][3], f.y, o01));
        f = up2(q0[2]); o00 = fmaf(C[0][1][0], f.x, fmaf(C[0][1][1], f.y, o00));
        f = up2(q0[3]); o01 = fmaf(C[0][1][2], f.x, fmaf(C[0][1][3], f.y, o01));
        f = up2(q1[0]); o10 = fmaf(C[1][0][0], f.x, fmaf(C[1][0][1], f.y, o10));
        f = up2(q1[1]); o11 = fmaf(C[1][0][2], f.x, fmaf(C[1][0][3], f.y, o11));
        f = up2(q1[2]); o10 = fmaf(C[1][1][0], f.x, fmaf(C[1][1][1], f.y, o10));
        f = up2(q1[3]); o11 = fmaf(C[1][1][2], f.x, fmaf(C[1][1][3], f.y, o11));
    }

    // Reduce the 4 j-phases within lane quads.
    o00 += __shfl_xor_sync(0xffffffffu, o00, 1);
    o00 += __shfl_xor_sync(0xffffffffu, o00, 2);
    o01 += __shfl_xor_sync(0xffffffffu, o01, 1);
    o01 += __shfl_xor_sync(0xffffffffu, o01, 2);
    o10 += __shfl_xor_sync(0xffffffffu, o10, 1);
    o10 += __shfl_xor_sync(0xffffffffu, o10, 2);
    o11 += __shfl_xor_sync(0xffffffffu, o11, 1);
    o11 += __shfl_xor_sync(0xffffffffu, o11, 2);

    // SR aliases B buffer 0 — fence all B reads (chunk 8 MMAs) first.
    __syncthreads();
    float* SR = reinterpret_cast<float*>(sm + SM_B);
    const int p = (h << 1) | kq;
    if ((lane & 3) == 0) {
        SR[p * BM + r0]      = o00;
        SR[p * BM + r0 + 8]  = o01;
        SR[p * BM + r0 + 16] = o10;
        SR[p * BM + r0 + 24] = o11;
    }
    __syncthreads();
    if (tid < BM)
        out[blockIdx.x * BM + tid] =
            (SR[tid] + SR[BM + tid]) + (SR[2 * BM + tid] + SR[3 * BM + tid]);
}

// ---------------------------------------------------------------------------
// Launch
// ---------------------------------------------------------------------------
extern "C" void kernel_launch(void* const* d_in, const int* in_sizes, int n_in,
                              void* d_out, int out_size) {
    const float* X = (const float*)d_in[0];   // x flat (xr[k][c] = X[k*NPTS+c])
    const float* M = (const float*)d_in[1];   // M_inv 286x286
    float* out = (float*)d_out;

    k_prep<<<NPTS / 256, 256>>>(M);

    cudaFuncSetAttribute(k_main, cudaFuncAttributeMaxDynamicSharedMemorySize,
                         SMEM_TOTAL);
    k_main<<<NPTS / BM, THREADS, SMEM_TOTAL>>>(X, out);
}